// round 1
// baseline (speedup 1.0000x reference)
#include <cuda_runtime.h>
#include <cstdint>

#define HID 256
#define MAXN 100000
#define MAXE 400000

// Scratch (device globals; no allocation allowed in kernel_launch)
__device__ float g_h0_node[(size_t)MAXN * HID];
__device__ float g_h_node [(size_t)MAXN * HID];
__device__ float g_h0_edge[(size_t)MAXE * HID];
__device__ float g_edge_a [(size_t)MAXE * HID];
__device__ float g_edge_b [(size_t)MAXE * HID];
__device__ float g_aggF   [(size_t)MAXN * HID];
__device__ float g_h2     [(size_t)MAXN * HID];

enum { MODE_IN2 = 0, MODE_MSG = 1, MODE_CAT3 = 2, MODE_OUT = 3 };

constexpr int BM = 64;   // rows per block
constexpr int KT = 32;   // K tile

// Generic N=256 SGEMM: C[M,256] = f(A[M,K] @ W[K,256])
// Block: 256 threads; warp w owns rows [w*8, w*8+8); lane owns cols {4l..4l+3, 128+4l..128+4l+3}
template<int MODE>
__global__ __launch_bounds__(256, 2)
void gemm_k(const float* __restrict__ A, const float* __restrict__ W,
            float* __restrict__ C, float* __restrict__ C2,
            const float* __restrict__ P1, const float* __restrict__ P2,
            const float* __restrict__ P3, const int* __restrict__ sidx,
            const float* __restrict__ bias, int M, int K)
{
    __shared__ float Ws[KT][HID];      // 32 KB
    __shared__ float As[KT][BM + 4];   // padded: conflict-limited stores, aligned LDS.128 broadcast
    const int tid  = threadIdx.x;
    const int lane = tid & 31;
    const int wgrp = tid >> 5;
    const int row0 = blockIdx.x * BM;
    const int rb   = wgrp * 8;
    const int cA   = lane * 4;

    float acc[8][8];
#pragma unroll
    for (int i = 0; i < 8; i++)
#pragma unroll
        for (int j = 0; j < 8; j++) acc[i][j] = 0.f;

    for (int k0 = 0; k0 < K; k0 += KT) {
        // ---- load W tile [KT x 256] (coalesced float4) ----
#pragma unroll
        for (int j = 0; j < 8; j++) {
            int idx = j * 256 + tid;        // 0..2047 float4 slots
            int kk  = idx >> 6;
            int c4  = (idx & 63) << 2;
            int kg  = k0 + kk;
            float4 v = make_float4(0.f, 0.f, 0.f, 0.f);
            if (kg < K) v = *(const float4*)&W[(size_t)kg * HID + c4];
            *(float4*)&Ws[kk][c4] = v;
        }
        // ---- load A tile transposed As[kk][r] (gmem coalesced in k) ----
#pragma unroll
        for (int j = 0; j < 8; j++) {
            int idx = j * 256 + tid;        // 0..2047 floats
            int r   = idx >> 5;
            int kk  = idx & 31;
            int grow = row0 + r;
            int gk   = k0 + kk;
            float v = 0.f;
            if (grow < M && gk < K) {
                if (MODE == MODE_IN2) {
                    v = A[(size_t)grow * K + gk];
                } else if (MODE == MODE_MSG) {
                    int s = __ldg(&sidx[grow]);
                    v = P1[(size_t)s * HID + gk] - P2[(size_t)(grow ^ 1) * HID + gk];
                } else if (MODE == MODE_CAT3) {
                    v = (gk < 256) ? P1[(size_t)grow * HID + gk]
                      : (gk < 512) ? P2[(size_t)grow * HID + (gk - 256)]
                                   : P3[(size_t)grow * HID + (gk - 512)];
                } else { // MODE_OUT
                    v = (gk < 256) ? P1[(size_t)grow * HID + gk]
                                   : P2[(size_t)grow * HID + (gk - 256)];
                }
            }
            As[kk][r] = v;
        }
        __syncthreads();

        // ---- 8x8 register micro-tile main loop ----
#pragma unroll 8
        for (int kk = 0; kk < KT; kk++) {
            float4 a0 = *(const float4*)&As[kk][rb];
            float4 a1 = *(const float4*)&As[kk][rb + 4];
            float4 w0 = *(const float4*)&Ws[kk][cA];
            float4 w1 = *(const float4*)&Ws[kk][128 + cA];
            float av[8] = {a0.x, a0.y, a0.z, a0.w, a1.x, a1.y, a1.z, a1.w};
            float wv[8] = {w0.x, w0.y, w0.z, w0.w, w1.x, w1.y, w1.z, w1.w};
#pragma unroll
            for (int i = 0; i < 8; i++)
#pragma unroll
                for (int j = 0; j < 8; j++)
                    acc[i][j] = fmaf(av[i], wv[j], acc[i][j]);
        }
        __syncthreads();
    }

    // ---- epilogue ----
#pragma unroll
    for (int i = 0; i < 8; i++) {
        int grow = row0 + rb + i;
        if (grow >= M) break;
        float o[8];
#pragma unroll
        for (int j = 0; j < 8; j++) o[j] = acc[i][j];
        if (MODE == MODE_MSG) {
            const float* h0 = &P3[(size_t)grow * HID];
#pragma unroll
            for (int j = 0; j < 4; j++) { o[j] += h0[cA + j]; o[4 + j] += h0[128 + cA + j]; }
        }
        if (MODE == MODE_OUT) {
#pragma unroll
            for (int j = 0; j < 4; j++) { o[j] += bias[cA + j]; o[4 + j] += bias[128 + cA + j]; }
        }
        if (MODE != MODE_CAT3) {
#pragma unroll
            for (int j = 0; j < 8; j++) o[j] = fmaxf(o[j], 0.f);
        }
        float4 v0 = make_float4(o[0], o[1], o[2], o[3]);
        float4 v1 = make_float4(o[4], o[5], o[6], o[7]);
        *(float4*)&C[(size_t)grow * HID + cA]        = v0;
        *(float4*)&C[(size_t)grow * HID + 128 + cA]  = v1;
        if (MODE == MODE_IN2 && C2 != nullptr) {
            *(float4*)&C2[(size_t)grow * HID + cA]       = v0;
            *(float4*)&C2[(size_t)grow * HID + 128 + cA] = v1;
        }
    }
}

// Segment-sum: acc[dst[e], :] += E[e, :]  via vector gmem reductions (no return)
__global__ void scatter_add_k(const float* __restrict__ E, const int* __restrict__ dst,
                              float* __restrict__ acc, int n_edges)
{
    int t = blockIdx.x * blockDim.x + threadIdx.x;
    int e = t >> 6;                 // 64 float4 lanes per edge row
    if (e >= n_edges) return;
    int c = (t & 63) << 2;
    float4 v = *(const float4*)&E[(size_t)e * HID + c];
    int d = __ldg(&dst[e]);
    float* p = &acc[(size_t)d * HID + c];
    asm volatile("red.global.add.v4.f32 [%0], {%1,%2,%3,%4};"
                 :: "l"(p), "f"(v.x), "f"(v.y), "f"(v.z), "f"(v.w) : "memory");
}

extern "C" void kernel_launch(void* const* d_in, const int* in_sizes, int n_in,
                              void* d_out, int out_size)
{
    const float* node_attr = (const float*)d_in[0];   // [N,133]
    const float* edge_attr = (const float*)d_in[1];   // [E,147]
    const int*   src       = (const int*)d_in[2];     // [E]
    const int*   dst       = (const int*)d_in[3];     // [E]
    const float* W_i_atom  = (const float*)d_in[4];   // [133,256]
    const float* W_i_bond  = (const float*)d_in[5];   // [147,256]
    const float* W_h       = (const float*)d_in[6];   // [3,256,256]
    const float* W_o       = (const float*)d_in[7];   // [512,256]
    const float* W_o_b     = (const float*)d_in[8];   // [256]
    const float* W_lr      = (const float*)d_in[9];   // [768,256]
    float* out = (float*)d_out;

    const int n_nodes = in_sizes[0] / 133;
    const int n_edges = in_sizes[2];

    float *h0n, *hn, *h0e, *ea, *eb, *agf, *h2;
    cudaGetSymbolAddress((void**)&h0n, g_h0_node);
    cudaGetSymbolAddress((void**)&hn,  g_h_node);
    cudaGetSymbolAddress((void**)&h0e, g_h0_edge);
    cudaGetSymbolAddress((void**)&ea,  g_edge_a);
    cudaGetSymbolAddress((void**)&eb,  g_edge_b);
    cudaGetSymbolAddress((void**)&agf, g_aggF);
    cudaGetSymbolAddress((void**)&h2,  g_h2);

    dim3 blk(256);
    const int gn = (n_nodes + BM - 1) / BM;
    const int ge = (n_edges + BM - 1) / BM;
    const int gs = (n_edges * 64 + 255) / 256;

    // Input projections: h0 = relu(x @ W_i); also seed running state copy
    gemm_k<MODE_IN2><<<gn, blk>>>(node_attr, W_i_atom, h0n, hn,
                                  nullptr, nullptr, nullptr, nullptr, nullptr, n_nodes, 133);
    gemm_k<MODE_IN2><<<ge, blk>>>(edge_attr, W_i_bond, h0e, ea,
                                  nullptr, nullptr, nullptr, nullptr, nullptr, n_edges, 147);

    float* cur = ea;
    float* nxt = eb;
    for (int d = 0; d < 3; d++) {
        // h_node += segment_sum(h_edge, dst)
        scatter_add_k<<<gs, 256>>>(cur, dst, hn, n_edges);
        // h_edge = relu(h0_edge + (h_node[src] - h_edge[rev]) @ W_h[d])  (gather fused in A-loader)
        gemm_k<MODE_MSG><<<ge, blk>>>(nullptr, W_h + (size_t)d * HID * HID, nxt, nullptr,
                                      hn, cur, h0e, src, nullptr, n_edges, 256);
        float* t = cur; cur = nxt; nxt = t;
    }

    // Final aggregation + readout
    cudaMemsetAsync(agf, 0, (size_t)n_nodes * HID * sizeof(float));
    scatter_add_k<<<gs, 256>>>(cur, dst, agf, n_edges);
    // h2 = [agg, h_node, h0_node] @ W_lr  (no activation, no bias)
    gemm_k<MODE_CAT3><<<gn, blk>>>(nullptr, W_lr, h2, nullptr,
                                   agf, hn, h0n, nullptr, nullptr, n_nodes, 768);
    // out = relu([h2, h0_node] @ W_o + b)
    gemm_k<MODE_OUT><<<gn, blk>>>(nullptr, W_o, out, nullptr,
                                  h2, h0n, nullptr, nullptr, W_o_b, n_nodes, 512);
}

// round 3
// speedup vs baseline: 1.9179x; 1.9179x over previous
#include <cuda_runtime.h>
#include <cuda_bf16.h>
#include <cstdint>

#define HID 256
#define MAXN 100000
#define MAXE 400000

// ---------------- scratch (device globals; no allocation allowed) ----------------
__device__ float g_h0_node[(size_t)MAXN * HID];
__device__ float g_h_node [(size_t)MAXN * HID];
__device__ float g_h0_edge[(size_t)MAXE * HID];
__device__ float g_edge_a [(size_t)MAXE * HID];
__device__ float g_edge_b [(size_t)MAXE * HID];
__device__ float g_aggF   [(size_t)MAXN * HID];
__device__ float g_h2     [(size_t)MAXN * HID];

// transposed + bf16-split weights: Wt[n][k], K-major, zero-padded to Kpad (mult of 32)
__device__ __align__(16) __nv_bfloat16 g_WtA_hi[(size_t)HID * 160];
__device__ __align__(16) __nv_bfloat16 g_WtA_lo[(size_t)HID * 160];
__device__ __align__(16) __nv_bfloat16 g_WtB_hi[(size_t)HID * 160];
__device__ __align__(16) __nv_bfloat16 g_WtB_lo[(size_t)HID * 160];
__device__ __align__(16) __nv_bfloat16 g_WtH_hi[(size_t)3 * HID * HID];
__device__ __align__(16) __nv_bfloat16 g_WtH_lo[(size_t)3 * HID * HID];
__device__ __align__(16) __nv_bfloat16 g_WtLR_hi[(size_t)HID * 768];
__device__ __align__(16) __nv_bfloat16 g_WtLR_lo[(size_t)HID * 768];
__device__ __align__(16) __nv_bfloat16 g_WtO_hi [(size_t)HID * 512];
__device__ __align__(16) __nv_bfloat16 g_WtO_lo [(size_t)HID * 512];

__device__ __forceinline__ uint32_t smem_u32(const void* p) {
    uint32_t a;
    asm("{ .reg .u64 t; cvta.to.shared.u64 t, %1; cvt.u32.u64 %0, t; }" : "=r"(a) : "l"(p));
    return a;
}

#define LDMX4(r, addr) \
    asm volatile("ldmatrix.sync.aligned.m8n8.x4.shared.b16 {%0,%1,%2,%3}, [%4];" \
        : "=r"((r)[0]), "=r"((r)[1]), "=r"((r)[2]), "=r"((r)[3]) : "r"(addr))

#define MMA(d, a, b0_, b1_) \
    asm volatile("mma.sync.aligned.m16n8k16.row.col.f32.bf16.bf16.f32 " \
        "{%0,%1,%2,%3}, {%4,%5,%6,%7}, {%8,%9}, {%0,%1,%2,%3};" \
        : "+f"((d)[0]), "+f"((d)[1]), "+f"((d)[2]), "+f"((d)[3]) \
        : "r"((a)[0]), "r"((a)[1]), "r"((a)[2]), "r"((a)[3]), "r"(b0_), "r"(b1_))

__device__ __forceinline__ uint32_t bfpack(__nv_bfloat16 x, __nv_bfloat16 y) {
    __nv_bfloat162 t = __halves2bfloat162(x, y);
    return reinterpret_cast<uint32_t&>(t);
}

enum { MODE_IN2 = 0, MODE_MSG = 1, MODE_CAT3 = 2, MODE_OUT = 3 };

// --------- bf16x3 tensor-core GEMM: C[M,256] = epi(A[M,K] @ W[K,256]) ---------
// Block tile 128(M) x 128(N), grid.y=2 covers N=256. 8 warps: 4(M) x 2(N), warp=32x64.
// smem rows: 128B = [hi 32bf16 | lo 32bf16] of one Kc=32 chunk, SW128 xor swizzle.
template<int MODE>
__global__ __launch_bounds__(256, 2)
void tgemm_k(const float* __restrict__ A,
             const __nv_bfloat16* __restrict__ Whi, const __nv_bfloat16* __restrict__ Wlo,
             float* __restrict__ C, float* __restrict__ C2,
             const float* __restrict__ P1, const float* __restrict__ P2,
             const float* __restrict__ P3, const int* __restrict__ sidx,
             const float* __restrict__ bias, int M, int K, int Kpad)
{
    __shared__ __align__(16) uint8_t sA[128 * 128];   // 16 KB
    __shared__ __align__(16) uint8_t sB[128 * 128];   // 16 KB
    const uint32_t sAu = smem_u32(sA);
    const uint32_t sBu = smem_u32(sB);

    const int tid  = threadIdx.x;
    const int lane = tid & 31;
    const int wid  = tid >> 5;
    const int wm   = wid & 3;          // 0..3 (M)
    const int wn   = wid >> 2;         // 0..1 (N)
    const int row0 = blockIdx.x * 128;
    const int nb   = blockIdx.y * 128; // weight row (output col) base

    float acc[2][8][4];
#pragma unroll
    for (int t = 0; t < 2; t++)
#pragma unroll
        for (int n = 0; n < 8; n++)
#pragma unroll
            for (int q = 0; q < 4; q++) acc[t][n][q] = 0.f;

    const int g  = lane >> 3;          // ldmatrix group
    const int i2 = lane & 7;
    const int nst = Kpad >> 5;

    for (int st = 0; st < nst; st++) {
        const int k0 = st << 5;
        // ---- stage A: 128 rows x 32 k, fp32 source -> bf16 hi/lo ----
#pragma unroll
        for (int it = 0; it < 2; it++) {
            int task = it * 256 + tid;     // 512 tasks: (row, chunk)
            int r = task >> 2, c = task & 3;
            int grow = row0 + r;
            float v[8];
#pragma unroll
            for (int j = 0; j < 8; j++) v[j] = 0.f;
            if (grow < M) {
                int gk = k0 + c * 8;
                if (MODE == MODE_IN2) {
                    const float* p = A + (size_t)grow * K + gk;
#pragma unroll
                    for (int j = 0; j < 8; j++) if (gk + j < K) v[j] = p[j];
                } else if (MODE == MODE_MSG) {
                    int s = __ldg(&sidx[grow]);
                    const float4* pa = (const float4*)(P1 + (size_t)s * HID + gk);
                    const float4* pb = (const float4*)(P2 + (size_t)(grow ^ 1) * HID + gk);
                    float4 a0 = pa[0], a1 = pa[1], b0 = pb[0], b1 = pb[1];
                    v[0] = a0.x - b0.x; v[1] = a0.y - b0.y; v[2] = a0.z - b0.z; v[3] = a0.w - b0.w;
                    v[4] = a1.x - b1.x; v[5] = a1.y - b1.y; v[6] = a1.z - b1.z; v[7] = a1.w - b1.w;
                } else {
                    const float* p;
                    if (MODE == MODE_CAT3) p = (gk < 256) ? P1 : (gk < 512) ? P2 : P3;
                    else                   p = (gk < 256) ? P1 : P2;
                    const float4* q4 = (const float4*)(p + (size_t)grow * HID + (gk & 255));
                    float4 a0 = q4[0], a1 = q4[1];
                    v[0] = a0.x; v[1] = a0.y; v[2] = a0.z; v[3] = a0.w;
                    v[4] = a1.x; v[5] = a1.y; v[6] = a1.z; v[7] = a1.w;
                }
            }
            uint32_t hi[4], lo[4];
#pragma unroll
            for (int j = 0; j < 4; j++) {
                float x = v[2 * j], y = v[2 * j + 1];
                __nv_bfloat16 hx = __float2bfloat16(x), hy = __float2bfloat16(y);
                float lx = x - __bfloat162float(hx), ly = y - __bfloat162float(hy);
                hi[j] = bfpack(hx, hy);
                hi[j] = hi[j];
                lo[j] = bfpack(__float2bfloat16(lx), __float2bfloat16(ly));
            }
            uint32_t rb = (uint32_t)r * 128;
            *(uint4*)(sA + rb + ((uint32_t)((c    ) ^ (r & 7)) << 4)) = make_uint4(hi[0], hi[1], hi[2], hi[3]);
            *(uint4*)(sA + rb + ((uint32_t)((c + 4) ^ (r & 7)) << 4)) = make_uint4(lo[0], lo[1], lo[2], lo[3]);
        }
        // ---- stage B: 128 n-rows x 32 k, pre-split bf16 gmem -> smem ----
#pragma unroll
        for (int it = 0; it < 4; it++) {
            int idx = it * 256 + tid;      // 1024 tasks: (var, row, chunk)
            int var = idx >> 9, rem = idx & 511;
            int r = rem >> 2, c = rem & 3;
            const __nv_bfloat16* W = var ? Wlo : Whi;
            uint4 d = *(const uint4*)(W + (size_t)(nb + r) * Kpad + k0 + c * 8);
            *(uint4*)(sB + (uint32_t)r * 128 + ((uint32_t)((var * 4 + c) ^ (r & 7)) << 4)) = d;
        }
        __syncthreads();

        // ---- compute: 2 x k16 chunks ----
#pragma unroll
        for (int kc = 0; kc < 2; kc++) {
            uint32_t ah[2][4], al[2][4];
#pragma unroll
            for (int t = 0; t < 2; t++) {
                int rowm = wm * 32 + t * 16 + (g & 1) * 8 + i2;
                uint32_t rb = (uint32_t)rowm * 128;
                LDMX4(ah[t], sAu + rb + ((uint32_t)((2 * kc + (g >> 1)    ) ^ (rowm & 7)) << 4));
                LDMX4(al[t], sAu + rb + ((uint32_t)((2 * kc + (g >> 1) + 4) ^ (rowm & 7)) << 4));
            }
#pragma unroll
            for (int p = 0; p < 4; p++) {
                int rn = wn * 64 + p * 16 + (g >> 1) * 8 + i2;
                uint32_t rb = (uint32_t)rn * 128;
                uint32_t bh[4], bl[4];
                LDMX4(bh, sBu + rb + ((uint32_t)((2 * kc + (g & 1)    ) ^ (rn & 7)) << 4));
                LDMX4(bl, sBu + rb + ((uint32_t)((2 * kc + (g & 1) + 4) ^ (rn & 7)) << 4));
#pragma unroll
                for (int t = 0; t < 2; t++) {
                    MMA(acc[t][2 * p],     ah[t], bh[0], bh[1]);
                    MMA(acc[t][2 * p + 1], ah[t], bh[2], bh[3]);
                    MMA(acc[t][2 * p],     ah[t], bl[0], bl[1]);
                    MMA(acc[t][2 * p + 1], ah[t], bl[2], bl[3]);
                    MMA(acc[t][2 * p],     al[t], bh[0], bh[1]);
                    MMA(acc[t][2 * p + 1], al[t], bh[2], bh[3]);
                }
            }
        }
        __syncthreads();
    }

    // ---- epilogue ----
    const int coln0 = nb + wn * 64;
#pragma unroll
    for (int t = 0; t < 2; t++) {
#pragma unroll
        for (int s = 0; s < 2; s++) {
            int row = row0 + wm * 32 + t * 16 + (lane >> 2) + s * 8;
            if (row >= M) continue;
#pragma unroll
            for (int n8 = 0; n8 < 8; n8++) {
                int col = coln0 + n8 * 8 + 2 * (lane & 3);
                float ox = acc[t][n8][2 * s], oy = acc[t][n8][2 * s + 1];
                if (MODE == MODE_MSG) {
                    float2 h = *(const float2*)(P3 + (size_t)row * HID + col);
                    ox += h.x; oy += h.y;
                }
                if (MODE == MODE_OUT) {
                    float2 b = *(const float2*)(bias + col);
                    ox += b.x; oy += b.y;
                }
                if (MODE != MODE_CAT3) { ox = fmaxf(ox, 0.f); oy = fmaxf(oy, 0.f); }
                float2 o = make_float2(ox, oy);
                *(float2*)(C + (size_t)row * HID + col) = o;
                if (MODE == MODE_IN2 && C2 != nullptr)
                    *(float2*)(C2 + (size_t)row * HID + col) = o;
            }
        }
    }
}

// ------- weight transpose + bf16 split: Wt[n][k] = W[k][n], zero-padded -------
__global__ void wsplit_k(const float* __restrict__ W, __nv_bfloat16* __restrict__ hi,
                         __nv_bfloat16* __restrict__ lo, int K, int Kpad)
{
    int idx = blockIdx.x * blockDim.x + threadIdx.x;
    if (idx >= HID * Kpad) return;
    int n = idx / Kpad, k = idx - n * Kpad;
    float v = (k < K) ? W[(size_t)k * HID + n] : 0.f;
    __nv_bfloat16 h = __float2bfloat16(v);
    hi[idx] = h;
    lo[idx] = __float2bfloat16(v - __bfloat162float(h));
}

// ------- segment-sum via vector gmem reductions (no return) -------
__global__ void scatter_add_k(const float* __restrict__ E, const int* __restrict__ dst,
                              float* __restrict__ acc, int n_edges)
{
    int t = blockIdx.x * blockDim.x + threadIdx.x;
    int e = t >> 6;
    if (e >= n_edges) return;
    int c = (t & 63) << 2;
    float4 v = *(const float4*)&E[(size_t)e * HID + c];
    int d = __ldg(&dst[e]);
    float* p = &acc[(size_t)d * HID + c];
    asm volatile("red.global.add.v4.f32 [%0], {%1,%2,%3,%4};"
                 :: "l"(p), "f"(v.x), "f"(v.y), "f"(v.z), "f"(v.w) : "memory");
}

extern "C" void kernel_launch(void* const* d_in, const int* in_sizes, int n_in,
                              void* d_out, int out_size)
{
    const float* node_attr = (const float*)d_in[0];
    const float* edge_attr = (const float*)d_in[1];
    const int*   src       = (const int*)d_in[2];
    const int*   dst       = (const int*)d_in[3];
    const float* W_i_atom  = (const float*)d_in[4];   // [133,256]
    const float* W_i_bond  = (const float*)d_in[5];   // [147,256]
    const float* W_h       = (const float*)d_in[6];   // [3,256,256]
    const float* W_o       = (const float*)d_in[7];   // [512,256]
    const float* W_o_b     = (const float*)d_in[8];   // [256]
    const float* W_lr      = (const float*)d_in[9];   // [768,256]
    float* out = (float*)d_out;

    const int KA = 133, KB = 147;
    const int n_nodes = in_sizes[0] / KA;
    const int n_edges = in_sizes[2];

    float *h0n, *hn, *h0e, *ea, *eb, *agf, *h2;
    __nv_bfloat16 *wahi, *walo, *wbhi, *wblo, *whhi, *whlo, *wlrhi, *wlrlo, *wohi, *wolo;
    cudaGetSymbolAddress((void**)&h0n, g_h0_node);
    cudaGetSymbolAddress((void**)&hn,  g_h_node);
    cudaGetSymbolAddress((void**)&h0e, g_h0_edge);
    cudaGetSymbolAddress((void**)&ea,  g_edge_a);
    cudaGetSymbolAddress((void**)&eb,  g_edge_b);
    cudaGetSymbolAddress((void**)&agf, g_aggF);
    cudaGetSymbolAddress((void**)&h2,  g_h2);
    cudaGetSymbolAddress((void**)&wahi, g_WtA_hi);   cudaGetSymbolAddress((void**)&walo, g_WtA_lo);
    cudaGetSymbolAddress((void**)&wbhi, g_WtB_hi);   cudaGetSymbolAddress((void**)&wblo, g_WtB_lo);
    cudaGetSymbolAddress((void**)&whhi, g_WtH_hi);   cudaGetSymbolAddress((void**)&whlo, g_WtH_lo);
    cudaGetSymbolAddress((void**)&wlrhi, g_WtLR_hi); cudaGetSymbolAddress((void**)&wlrlo, g_WtLR_lo);
    cudaGetSymbolAddress((void**)&wohi, g_WtO_hi);   cudaGetSymbolAddress((void**)&wolo, g_WtO_lo);

    const int KAp = 160, KBp = 160;

    // transpose + split weights (bf16 hi/lo)
    {
        dim3 b(256);
        wsplit_k<<<(HID * KAp + 255) / 256, b>>>(W_i_atom, wahi, walo, KA, KAp);
        wsplit_k<<<(HID * KBp + 255) / 256, b>>>(W_i_bond, wbhi, wblo, KB, KBp);
        for (int d = 0; d < 3; d++)
            wsplit_k<<<(HID * HID + 255) / 256, b>>>(W_h + (size_t)d * HID * HID,
                                                     whhi + (size_t)d * HID * HID,
                                                     whlo + (size_t)d * HID * HID, HID, HID);
        wsplit_k<<<(HID * 768 + 255) / 256, b>>>(W_lr, wlrhi, wlrlo, 768, 768);
        wsplit_k<<<(HID * 512 + 255) / 256, b>>>(W_o,  wohi,  wolo,  512, 512);
    }

    dim3 blk(256);
    dim3 gn((n_nodes + 127) / 128, 2);
    dim3 ge((n_edges + 127) / 128, 2);
    const int gs = (n_edges * 64 + 255) / 256;

    // input projections: h0 = relu(x @ W_i); node one also seeds h_node
    tgemm_k<MODE_IN2><<<gn, blk>>>(node_attr, wahi, walo, h0n, hn,
        nullptr, nullptr, nullptr, nullptr, nullptr, n_nodes, KA, KAp);
    tgemm_k<MODE_IN2><<<ge, blk>>>(edge_attr, wbhi, wblo, h0e, nullptr,
        nullptr, nullptr, nullptr, nullptr, nullptr, n_edges, KB, KBp);

    float* bufs[2] = {ea, eb};
    float* cur = h0e;
    for (int d = 0; d < 3; d++) {
        float* nxt = bufs[d & 1];
        // h_node += segment_sum(h_edge, dst)
        scatter_add_k<<<gs, 256>>>(cur, dst, hn, n_edges);
        // h_edge = relu(h0_edge + (h_node[src] - h_edge[rev]) @ W_h[d])
        tgemm_k<MODE_MSG><<<ge, blk>>>(nullptr,
            whhi + (size_t)d * HID * HID, whlo + (size_t)d * HID * HID, nxt, nullptr,
            hn, cur, h0e, src, nullptr, n_edges, HID, HID);
        cur = nxt;
    }

    cudaMemsetAsync(agf, 0, (size_t)n_nodes * HID * sizeof(float));
    scatter_add_k<<<gs, 256>>>(cur, dst, agf, n_edges);
    // h2 = [agg, h_node, h0_node] @ W_lr (linear)
    tgemm_k<MODE_CAT3><<<gn, blk>>>(nullptr, wlrhi, wlrlo, h2, nullptr,
        agf, hn, h0n, nullptr, nullptr, n_nodes, 768, 768);
    // out = relu([h2, h0_node] @ W_o + b)
    tgemm_k<MODE_OUT><<<gn, blk>>>(nullptr, wohi, wolo, out, nullptr,
        h2, h0n, nullptr, nullptr, W_o_b, n_nodes, 512, 512);
}

// round 4
// speedup vs baseline: 2.0553x; 1.0716x over previous
#include <cuda_runtime.h>
#include <cuda_bf16.h>
#include <cstdint>

#define HID 256
#define MAXN 100000
#define MAXE 400000

// ---------------- scratch (device globals; no allocation allowed) ----------------
__device__ float g_h0_node[(size_t)MAXN * HID];
__device__ float g_hnA    [(size_t)MAXN * HID];
__device__ float g_hnB    [(size_t)MAXN * HID];
__device__ float g_h0_edge[(size_t)MAXE * HID];
__device__ float g_edge_a [(size_t)MAXE * HID];
__device__ float g_edge_b [(size_t)MAXE * HID];
__device__ float g_aggF   [(size_t)MAXN * HID];
__device__ float g_h2     [(size_t)MAXN * HID];

// transposed + bf16-split weights: Wt[n][k], K-major, zero-padded to Kpad
__device__ __align__(16) __nv_bfloat16 g_WtA_hi[(size_t)HID * 160];
__device__ __align__(16) __nv_bfloat16 g_WtA_lo[(size_t)HID * 160];
__device__ __align__(16) __nv_bfloat16 g_WtB_hi[(size_t)HID * 160];
__device__ __align__(16) __nv_bfloat16 g_WtB_lo[(size_t)HID * 160];
__device__ __align__(16) __nv_bfloat16 g_WtH_hi[(size_t)3 * HID * HID];
__device__ __align__(16) __nv_bfloat16 g_WtH_lo[(size_t)3 * HID * HID];
__device__ __align__(16) __nv_bfloat16 g_WtLR_hi[(size_t)HID * 768];
__device__ __align__(16) __nv_bfloat16 g_WtLR_lo[(size_t)HID * 768];
__device__ __align__(16) __nv_bfloat16 g_WtO_hi [(size_t)HID * 512];
__device__ __align__(16) __nv_bfloat16 g_WtO_lo [(size_t)HID * 512];

__device__ __forceinline__ uint32_t smem_u32(const void* p) {
    uint32_t a;
    asm("{ .reg .u64 t; cvta.to.shared.u64 t, %1; cvt.u32.u64 %0, t; }" : "=r"(a) : "l"(p));
    return a;
}

#define LDMX4(r, addr) \
    asm volatile("ldmatrix.sync.aligned.m8n8.x4.shared.b16 {%0,%1,%2,%3}, [%4];" \
        : "=r"((r)[0]), "=r"((r)[1]), "=r"((r)[2]), "=r"((r)[3]) : "r"(addr))

#define MMA(d, a, b0_, b1_) \
    asm volatile("mma.sync.aligned.m16n8k16.row.col.f32.bf16.bf16.f32 " \
        "{%0,%1,%2,%3}, {%4,%5,%6,%7}, {%8,%9}, {%0,%1,%2,%3};" \
        : "+f"((d)[0]), "+f"((d)[1]), "+f"((d)[2]), "+f"((d)[3]) \
        : "r"((a)[0]), "r"((a)[1]), "r"((a)[2]), "r"((a)[3]), "r"(b0_), "r"(b1_))

__device__ __forceinline__ uint32_t bfpack(__nv_bfloat16 x, __nv_bfloat16 y) {
    __nv_bfloat162 t = __halves2bfloat162(x, y);
    return reinterpret_cast<uint32_t&>(t);
}

enum { MODE_IN2 = 0, MODE_MSG = 1, MODE_CAT3 = 2, MODE_OUT = 3 };

constexpr int SMEM_BYTES = 65536;   // A0|A1|B0|B1 x 16KB

// --------- bf16x3 tensor-core GEMM, double-buffered pipeline, fused scatter-RED ---------
// Block tile 128(M) x 128(N), grid.y=2 covers N=256. 8 warps: 4(M) x 2(N).
template<int MODE, bool RED_, bool WRITE_>
__global__ __launch_bounds__(256, 2)
void tgemm_k(const float* __restrict__ A,
             const __nv_bfloat16* __restrict__ Whi, const __nv_bfloat16* __restrict__ Wlo,
             float* __restrict__ C, float* __restrict__ C2, float* __restrict__ R,
             const int* __restrict__ ridx,
             const float* __restrict__ P1, const float* __restrict__ P2,
             const float* __restrict__ P3, const int* __restrict__ sidx,
             const float* __restrict__ bias, int M, int K, int Kpad)
{
    extern __shared__ __align__(16) uint8_t smem[];
    uint8_t* sA = smem;
    uint8_t* sB = smem + 32768;
    const uint32_t sAu = smem_u32(sA);
    const uint32_t sBu = smem_u32(sB);

    const int tid  = threadIdx.x;
    const int lane = tid & 31;
    const int wid  = tid >> 5;
    const int wm   = wid & 3;
    const int wn   = wid >> 2;
    const int row0 = blockIdx.x * 128;
    const int nb   = blockIdx.y * 128;

    float acc[2][8][4];
#pragma unroll
    for (int t = 0; t < 2; t++)
#pragma unroll
        for (int n = 0; n < 8; n++)
#pragma unroll
            for (int q = 0; q < 4; q++) acc[t][n][q] = 0.f;

    const int g  = lane >> 3;
    const int i2 = lane & 7;
    const int nst = Kpad >> 5;

    auto stage = [&](int st, int buf) {
        const int k0 = st << 5;
        uint8_t* dA = sA + (uint32_t)buf * 16384u;
        uint8_t* dB = sB + (uint32_t)buf * 16384u;
#pragma unroll
        for (int it = 0; it < 2; it++) {
            int task = it * 256 + tid;
            int r = task >> 2, c = task & 3;
            int grow = row0 + r;
            float v[8];
#pragma unroll
            for (int j = 0; j < 8; j++) v[j] = 0.f;
            if (grow < M) {
                int gk = k0 + c * 8;
                if (MODE == MODE_IN2) {
                    const float* p = A + (size_t)grow * K + gk;
#pragma unroll
                    for (int j = 0; j < 8; j++) if (gk + j < K) v[j] = p[j];
                } else if (MODE == MODE_MSG) {
                    int s = __ldg(&sidx[grow]);
                    const float4* pa = (const float4*)(P1 + (size_t)s * HID + gk);
                    const float4* pb = (const float4*)(P2 + (size_t)(grow ^ 1) * HID + gk);
                    float4 a0 = pa[0], a1 = pa[1], b0 = pb[0], b1 = pb[1];
                    v[0] = a0.x - b0.x; v[1] = a0.y - b0.y; v[2] = a0.z - b0.z; v[3] = a0.w - b0.w;
                    v[4] = a1.x - b1.x; v[5] = a1.y - b1.y; v[6] = a1.z - b1.z; v[7] = a1.w - b1.w;
                } else {
                    const float* p;
                    if (MODE == MODE_CAT3) p = (gk < 256) ? P1 : (gk < 512) ? P2 : P3;
                    else                   p = (gk < 256) ? P1 : P2;
                    const float4* q4 = (const float4*)(p + (size_t)grow * HID + (gk & 255));
                    float4 a0 = q4[0], a1 = q4[1];
                    v[0] = a0.x; v[1] = a0.y; v[2] = a0.z; v[3] = a0.w;
                    v[4] = a1.x; v[5] = a1.y; v[6] = a1.z; v[7] = a1.w;
                }
            }
            uint32_t hi[4], lo[4];
#pragma unroll
            for (int j = 0; j < 4; j++) {
                float x = v[2 * j], y = v[2 * j + 1];
                __nv_bfloat16 hx = __float2bfloat16(x), hy = __float2bfloat16(y);
                float lx = x - __bfloat162float(hx), ly = y - __bfloat162float(hy);
                hi[j] = bfpack(hx, hy);
                lo[j] = bfpack(__float2bfloat16(lx), __float2bfloat16(ly));
            }
            uint32_t rb = (uint32_t)r * 128;
            *(uint4*)(dA + rb + ((uint32_t)((c    ) ^ (r & 7)) << 4)) = make_uint4(hi[0], hi[1], hi[2], hi[3]);
            *(uint4*)(dA + rb + ((uint32_t)((c + 4) ^ (r & 7)) << 4)) = make_uint4(lo[0], lo[1], lo[2], lo[3]);
        }
#pragma unroll
        for (int it = 0; it < 4; it++) {
            int idx = it * 256 + tid;
            int var = idx >> 9, rem = idx & 511;
            int r = rem >> 2, c = rem & 3;
            const __nv_bfloat16* W = var ? Wlo : Whi;
            uint4 d = *(const uint4*)(W + (size_t)(nb + r) * Kpad + k0 + c * 8);
            *(uint4*)(dB + (uint32_t)r * 128 + ((uint32_t)((var * 4 + c) ^ (r & 7)) << 4)) = d;
        }
    };

    stage(0, 0);
    __syncthreads();

    for (int st = 0; st < nst; st++) {
        const int buf = st & 1;
        if (st + 1 < nst) stage(st + 1, buf ^ 1);

        const uint32_t aBase = sAu + (uint32_t)buf * 16384u;
        const uint32_t bBase = sBu + (uint32_t)buf * 16384u;
#pragma unroll
        for (int kc = 0; kc < 2; kc++) {
            uint32_t ah[2][4], al[2][4];
#pragma unroll
            for (int t = 0; t < 2; t++) {
                int rowm = wm * 32 + t * 16 + (g & 1) * 8 + i2;
                uint32_t rb = (uint32_t)rowm * 128;
                LDMX4(ah[t], aBase + rb + ((uint32_t)((2 * kc + (g >> 1)    ) ^ (rowm & 7)) << 4));
                LDMX4(al[t], aBase + rb + ((uint32_t)((2 * kc + (g >> 1) + 4) ^ (rowm & 7)) << 4));
            }
#pragma unroll
            for (int p = 0; p < 4; p++) {
                int rn = wn * 64 + p * 16 + (g >> 1) * 8 + i2;
                uint32_t rb = (uint32_t)rn * 128;
                uint32_t bh[4], bl[4];
                LDMX4(bh, bBase + rb + ((uint32_t)((2 * kc + (g & 1)    ) ^ (rn & 7)) << 4));
                LDMX4(bl, bBase + rb + ((uint32_t)((2 * kc + (g & 1) + 4) ^ (rn & 7)) << 4));
#pragma unroll
                for (int t = 0; t < 2; t++) {
                    MMA(acc[t][2 * p],     ah[t], bh[0], bh[1]);
                    MMA(acc[t][2 * p + 1], ah[t], bh[2], bh[3]);
                    MMA(acc[t][2 * p],     ah[t], bl[0], bl[1]);
                    MMA(acc[t][2 * p + 1], ah[t], bl[2], bl[3]);
                    MMA(acc[t][2 * p],     al[t], bh[0], bh[1]);
                    MMA(acc[t][2 * p + 1], al[t], bh[2], bh[3]);
                }
            }
        }
        __syncthreads();
    }

    // ---- epilogue: write C and/or scatter-RED into R[ridx[row]] ----
    const int coln0 = nb + wn * 64;
#pragma unroll
    for (int t = 0; t < 2; t++) {
#pragma unroll
        for (int s = 0; s < 2; s++) {
            int row = row0 + wm * 32 + t * 16 + (lane >> 2) + s * 8;
            if (row >= M) continue;
            int drow = 0;
            if (RED_) drow = __ldg(&ridx[row]);
#pragma unroll
            for (int n8 = 0; n8 < 8; n8++) {
                int col = coln0 + n8 * 8 + 2 * (lane & 3);
                float ox = acc[t][n8][2 * s], oy = acc[t][n8][2 * s + 1];
                if (MODE == MODE_MSG) {
                    float2 h = *(const float2*)(P3 + (size_t)row * HID + col);
                    ox += h.x; oy += h.y;
                }
                if (MODE == MODE_OUT) {
                    float2 b = *(const float2*)(bias + col);
                    ox += b.x; oy += b.y;
                }
                if (MODE != MODE_CAT3) { ox = fmaxf(ox, 0.f); oy = fmaxf(oy, 0.f); }
                if (WRITE_) {
                    float2 o = make_float2(ox, oy);
                    *(float2*)(C + (size_t)row * HID + col) = o;
                    if (MODE == MODE_IN2 && C2 != nullptr)
                        *(float2*)(C2 + (size_t)row * HID + col) = o;
                }
                if (RED_) {
                    float* p = R + (size_t)drow * HID + col;
                    asm volatile("red.global.add.v2.f32 [%0], {%1,%2};"
                                 :: "l"(p), "f"(ox), "f"(oy) : "memory");
                }
            }
        }
    }
}

__global__ void wsplit_k(const float* __restrict__ W, __nv_bfloat16* __restrict__ hi,
                         __nv_bfloat16* __restrict__ lo, int K, int Kpad)
{
    int idx = blockIdx.x * blockDim.x + threadIdx.x;
    if (idx >= HID * Kpad) return;
    int n = idx / Kpad, k = idx - n * Kpad;
    float v = (k < K) ? W[(size_t)k * HID + n] : 0.f;
    __nv_bfloat16 h = __float2bfloat16(v);
    hi[idx] = h;
    lo[idx] = __float2bfloat16(v - __bfloat162float(h));
}

__global__ void copy_k(const float4* __restrict__ src, float4* __restrict__ dst, int n4)
{
    int i = blockIdx.x * blockDim.x + threadIdx.x;
    if (i < n4) dst[i] = src[i];
}

extern "C" void kernel_launch(void* const* d_in, const int* in_sizes, int n_in,
                              void* d_out, int out_size)
{
    const float* node_attr = (const float*)d_in[0];
    const float* edge_attr = (const float*)d_in[1];
    const int*   src       = (const int*)d_in[2];
    const int*   dst       = (const int*)d_in[3];
    const float* W_i_atom  = (const float*)d_in[4];
    const float* W_i_bond  = (const float*)d_in[5];
    const float* W_h       = (const float*)d_in[6];
    const float* W_o       = (const float*)d_in[7];
    const float* W_o_b     = (const float*)d_in[8];
    const float* W_lr      = (const float*)d_in[9];
    float* out = (float*)d_out;

    const int KA = 133, KB = 147;
    const int n_nodes = in_sizes[0] / KA;
    const int n_edges = in_sizes[2];

    float *h0n, *hnA, *hnB, *h0e, *ea, *eb, *agf, *h2;
    __nv_bfloat16 *wahi, *walo, *wbhi, *wblo, *whhi, *whlo, *wlrhi, *wlrlo, *wohi, *wolo;
    cudaGetSymbolAddress((void**)&h0n, g_h0_node);
    cudaGetSymbolAddress((void**)&hnA, g_hnA);
    cudaGetSymbolAddress((void**)&hnB, g_hnB);
    cudaGetSymbolAddress((void**)&h0e, g_h0_edge);
    cudaGetSymbolAddress((void**)&ea,  g_edge_a);
    cudaGetSymbolAddress((void**)&eb,  g_edge_b);
    cudaGetSymbolAddress((void**)&agf, g_aggF);
    cudaGetSymbolAddress((void**)&h2,  g_h2);
    cudaGetSymbolAddress((void**)&wahi, g_WtA_hi);   cudaGetSymbolAddress((void**)&walo, g_WtA_lo);
    cudaGetSymbolAddress((void**)&wbhi, g_WtB_hi);   cudaGetSymbolAddress((void**)&wblo, g_WtB_lo);
    cudaGetSymbolAddress((void**)&whhi, g_WtH_hi);   cudaGetSymbolAddress((void**)&whlo, g_WtH_lo);
    cudaGetSymbolAddress((void**)&wlrhi, g_WtLR_hi); cudaGetSymbolAddress((void**)&wlrlo, g_WtLR_lo);
    cudaGetSymbolAddress((void**)&wohi, g_WtO_hi);   cudaGetSymbolAddress((void**)&wolo, g_WtO_lo);

    cudaFuncSetAttribute((const void*)tgemm_k<MODE_IN2,  false, true >, cudaFuncAttributeMaxDynamicSharedMemorySize, SMEM_BYTES);
    cudaFuncSetAttribute((const void*)tgemm_k<MODE_IN2,  true,  true >, cudaFuncAttributeMaxDynamicSharedMemorySize, SMEM_BYTES);
    cudaFuncSetAttribute((const void*)tgemm_k<MODE_MSG,  true,  true >, cudaFuncAttributeMaxDynamicSharedMemorySize, SMEM_BYTES);
    cudaFuncSetAttribute((const void*)tgemm_k<MODE_MSG,  true,  false>, cudaFuncAttributeMaxDynamicSharedMemorySize, SMEM_BYTES);
    cudaFuncSetAttribute((const void*)tgemm_k<MODE_CAT3, false, true >, cudaFuncAttributeMaxDynamicSharedMemorySize, SMEM_BYTES);
    cudaFuncSetAttribute((const void*)tgemm_k<MODE_OUT,  false, true >, cudaFuncAttributeMaxDynamicSharedMemorySize, SMEM_BYTES);

    const int KAp = 160, KBp = 160;
    {
        dim3 b(256);
        wsplit_k<<<(HID * KAp + 255) / 256, b>>>(W_i_atom, wahi, walo, KA, KAp);
        wsplit_k<<<(HID * KBp + 255) / 256, b>>>(W_i_bond, wbhi, wblo, KB, KBp);
        for (int d = 0; d < 3; d++)
            wsplit_k<<<(HID * HID + 255) / 256, b>>>(W_h + (size_t)d * HID * HID,
                                                     whhi + (size_t)d * HID * HID,
                                                     whlo + (size_t)d * HID * HID, HID, HID);
        wsplit_k<<<(HID * 768 + 255) / 256, b>>>(W_lr, wlrhi, wlrlo, 768, 768);
        wsplit_k<<<(HID * 512 + 255) / 256, b>>>(W_o,  wohi,  wolo,  512, 512);
    }

    dim3 blk(256);
    dim3 gn((n_nodes + 127) / 128, 2);
    dim3 ge((n_edges + 127) / 128, 2);
    const int n4n = n_nodes * HID / 4;
    const int cpg = (n4n + 255) / 256;

    // node proj: h0n = relu(x@Wa); C2 seeds hnA = h0n
    tgemm_k<MODE_IN2, false, true><<<gn, blk, SMEM_BYTES>>>(node_attr, wahi, walo,
        h0n, hnA, nullptr, nullptr, nullptr, nullptr, nullptr, nullptr, nullptr, n_nodes, KA, KAp);
    // edge proj: h0e = relu(x@Wb); RED h0e rows into hnA[dst] -> hnA = hn after agg0
    tgemm_k<MODE_IN2, true, true><<<ge, blk, SMEM_BYTES>>>(edge_attr, wbhi, wblo,
        h0e, nullptr, hnA, dst, nullptr, nullptr, nullptr, nullptr, nullptr, n_edges, KB, KBp);

    // depth 0: read hnA(src), h0e(rev); write ea; RED ea into hnB[dst] (hnB pre-seeded = hnA)
    copy_k<<<cpg, 256>>>((const float4*)hnA, (float4*)hnB, n4n);
    tgemm_k<MODE_MSG, true, true><<<ge, blk, SMEM_BYTES>>>(nullptr,
        whhi + 0 * (size_t)HID * HID, whlo + 0 * (size_t)HID * HID,
        ea, nullptr, hnB, dst, hnA, h0e, h0e, src, nullptr, n_edges, HID, HID);
    // depth 1: read hnB(src), ea(rev); write eb; RED into hnA (pre-seeded = hnB)
    copy_k<<<cpg, 256>>>((const float4*)hnB, (float4*)hnA, n4n);
    tgemm_k<MODE_MSG, true, true><<<ge, blk, SMEM_BYTES>>>(nullptr,
        whhi + 1 * (size_t)HID * HID, whlo + 1 * (size_t)HID * HID,
        eb, nullptr, hnA, dst, hnB, ea, h0e, src, nullptr, n_edges, HID, HID);
    // depth 2: read hnA(src), eb(rev); no C write; RED into agf (zeroed)
    cudaMemsetAsync(agf, 0, (size_t)n_nodes * HID * sizeof(float));
    tgemm_k<MODE_MSG, true, false><<<ge, blk, SMEM_BYTES>>>(nullptr,
        whhi + 2 * (size_t)HID * HID, whlo + 2 * (size_t)HID * HID,
        nullptr, nullptr, agf, dst, hnA, eb, h0e, src, nullptr, n_edges, HID, HID);

    // readout: h2 = [agf, hnA, h0n] @ W_lr ; out = relu([h2, h0n] @ W_o + b)
    tgemm_k<MODE_CAT3, false, true><<<gn, blk, SMEM_BYTES>>>(nullptr, wlrhi, wlrlo,
        h2, nullptr, nullptr, nullptr, agf, hnA, h0n, nullptr, nullptr, n_nodes, 768, 768);
    tgemm_k<MODE_OUT, false, true><<<gn, blk, SMEM_BYTES>>>(nullptr, wohi, wolo,
        out, nullptr, nullptr, nullptr, h2, h0n, nullptr, nullptr, W_o_b, n_nodes, 512, 512);
}

// round 5
// speedup vs baseline: 2.1299x; 1.0363x over previous
#include <cuda_runtime.h>
#include <cuda_bf16.h>
#include <cstdint>

#define HID 256
#define MAXN 100000
#define MAXE 400000

// ---------------- scratch (device globals; no allocation allowed) ----------------
__device__ float g_h0_node[(size_t)MAXN * HID];
__device__ float g_hnA    [(size_t)MAXN * HID];
__device__ float g_hnB    [(size_t)MAXN * HID];
__device__ float g_h0_edge[(size_t)MAXE * HID];
__device__ float g_edge_a [(size_t)MAXE * HID];
__device__ float g_edge_b [(size_t)MAXE * HID];
__device__ float g_aggF   [(size_t)MAXN * HID];
__device__ float g_h2     [(size_t)MAXN * HID];

// transposed + bf16-split weights: Wt[n][k], K-major, zero-padded to Kpad
__device__ __align__(16) __nv_bfloat16 g_WtA_hi[(size_t)HID * 160];
__device__ __align__(16) __nv_bfloat16 g_WtA_lo[(size_t)HID * 160];
__device__ __align__(16) __nv_bfloat16 g_WtB_hi[(size_t)HID * 160];
__device__ __align__(16) __nv_bfloat16 g_WtB_lo[(size_t)HID * 160];
__device__ __align__(16) __nv_bfloat16 g_WtH_hi[(size_t)3 * HID * HID];
__device__ __align__(16) __nv_bfloat16 g_WtH_lo[(size_t)3 * HID * HID];
__device__ __align__(16) __nv_bfloat16 g_WtLR_hi[(size_t)HID * 768];
__device__ __align__(16) __nv_bfloat16 g_WtLR_lo[(size_t)HID * 768];
__device__ __align__(16) __nv_bfloat16 g_WtO_hi [(size_t)HID * 512];
__device__ __align__(16) __nv_bfloat16 g_WtO_lo [(size_t)HID * 512];

__device__ __forceinline__ uint32_t smem_u32(const void* p) {
    uint32_t a;
    asm("{ .reg .u64 t; cvta.to.shared.u64 t, %1; cvt.u32.u64 %0, t; }" : "=r"(a) : "l"(p));
    return a;
}

#define LDMX4(r, addr) \
    asm volatile("ldmatrix.sync.aligned.m8n8.x4.shared.b16 {%0,%1,%2,%3}, [%4];" \
        : "=r"((r)[0]), "=r"((r)[1]), "=r"((r)[2]), "=r"((r)[3]) : "r"(addr))

#define MMA(d, a, b0_, b1_) \
    asm volatile("mma.sync.aligned.m16n8k16.row.col.f32.bf16.bf16.f32 " \
        "{%0,%1,%2,%3}, {%4,%5,%6,%7}, {%8,%9}, {%0,%1,%2,%3};" \
        : "+f"((d)[0]), "+f"((d)[1]), "+f"((d)[2]), "+f"((d)[3]) \
        : "r"((a)[0]), "r"((a)[1]), "r"((a)[2]), "r"((a)[3]), "r"(b0_), "r"(b1_))

#define CPA16(dst_u32, src_ptr) \
    asm volatile("cp.async.cg.shared.global [%0], [%1], 16;" \
        :: "r"(dst_u32), "l"(src_ptr) : "memory")
#define CPA_COMMIT() asm volatile("cp.async.commit_group;" ::: "memory")
#define CPA_WAIT0()  asm volatile("cp.async.wait_group 0;" ::: "memory")

__device__ __forceinline__ uint32_t bfpack(__nv_bfloat16 x, __nv_bfloat16 y) {
    __nv_bfloat162 t = __halves2bfloat162(x, y);
    return reinterpret_cast<uint32_t&>(t);
}

enum { MODE_IN2 = 0, MODE_MSG = 1, MODE_CAT3 = 2, MODE_OUT = 3 };

constexpr int SMEM_BYTES = 65536;   // A0|A1 (32K) | B0|B1 (32K)

// --------- bf16x3 tensor-core GEMM, double-buffered pipeline, fused scatter-RED ---------
// Block tile 128(M) x 128(N), grid.y=2 covers N=256. 8 warps: 4(M) x 2(N).
template<int MODE, bool RED_, bool WRITE_>
__global__ __launch_bounds__(256, 2)
void tgemm_k(const float* __restrict__ A,
             const __nv_bfloat16* __restrict__ Whi, const __nv_bfloat16* __restrict__ Wlo,
             float* __restrict__ C, float* __restrict__ C2, float* __restrict__ R,
             const int* __restrict__ ridx,
             const float* __restrict__ P1, const float* __restrict__ P2,
             const float* __restrict__ P3, const int* __restrict__ sidx,
             const float* __restrict__ bias, int M, int K, int Kpad)
{
    extern __shared__ __align__(16) uint8_t smem[];
    uint8_t* sA = smem;
    const uint32_t sAu = smem_u32(smem);
    const uint32_t sBu = sAu + 32768;

    const int tid  = threadIdx.x;
    const int lane = tid & 31;
    const int wid  = tid >> 5;
    const int wm   = wid & 3;
    const int wn   = wid >> 2;
    const int row0 = blockIdx.x * 128;
    const int nb   = blockIdx.y * 128;

    float acc[2][8][4];
#pragma unroll
    for (int t = 0; t < 2; t++)
#pragma unroll
        for (int n = 0; n < 8; n++)
#pragma unroll
            for (int q = 0; q < 4; q++) acc[t][n][q] = 0.f;

    const int g  = lane >> 3;
    const int i2 = lane & 7;
    const int nst = Kpad >> 5;

    // stage A (fp32 sources -> bf16 hi/lo, manual) and B (pre-split bf16, cp.async)
    auto stage = [&](int st, int buf) {
        const int k0 = st << 5;
        uint8_t* dA = sA + (uint32_t)buf * 16384u;
        const uint32_t dBu = sBu + (uint32_t)buf * 16384u;
        // B first: get cp.async in flight early
#pragma unroll
        for (int it = 0; it < 4; it++) {
            int idx = it * 256 + tid;
            int var = idx >> 9, rem = idx & 511;
            int r = rem >> 2, c = rem & 3;
            const __nv_bfloat16* W = var ? Wlo : Whi;
            const __nv_bfloat16* src = W + (size_t)(nb + r) * Kpad + k0 + c * 8;
            uint32_t dst = dBu + (uint32_t)r * 128 + ((uint32_t)((var * 4 + c) ^ (r & 7)) << 4);
            CPA16(dst, src);
        }
        CPA_COMMIT();
        // A: gather/concat/subtract + split
#pragma unroll
        for (int it = 0; it < 2; it++) {
            int task = it * 256 + tid;
            int r = task >> 2, c = task & 3;
            int grow = row0 + r;
            float v[8];
#pragma unroll
            for (int j = 0; j < 8; j++) v[j] = 0.f;
            if (grow < M) {
                int gk = k0 + c * 8;
                if (MODE == MODE_IN2) {
                    const float* p = A + (size_t)grow * K + gk;
#pragma unroll
                    for (int j = 0; j < 8; j++) if (gk + j < K) v[j] = p[j];
                } else if (MODE == MODE_MSG) {
                    int s = __ldg(&sidx[grow]);
                    const float4* pa = (const float4*)(P1 + (size_t)s * HID + gk);
                    const float4* pb = (const float4*)(P2 + (size_t)(grow ^ 1) * HID + gk);
                    float4 a0 = pa[0], a1 = pa[1], b0 = pb[0], b1 = pb[1];
                    v[0] = a0.x - b0.x; v[1] = a0.y - b0.y; v[2] = a0.z - b0.z; v[3] = a0.w - b0.w;
                    v[4] = a1.x - b1.x; v[5] = a1.y - b1.y; v[6] = a1.z - b1.z; v[7] = a1.w - b1.w;
                } else {
                    const float* p;
                    if (MODE == MODE_CAT3) p = (gk < 256) ? P1 : (gk < 512) ? P2 : P3;
                    else                   p = (gk < 256) ? P1 : P2;
                    const float4* q4 = (const float4*)(p + (size_t)grow * HID + (gk & 255));
                    float4 a0 = q4[0], a1 = q4[1];
                    v[0] = a0.x; v[1] = a0.y; v[2] = a0.z; v[3] = a0.w;
                    v[4] = a1.x; v[5] = a1.y; v[6] = a1.z; v[7] = a1.w;
                }
            }
            uint32_t hi[4], lo[4];
#pragma unroll
            for (int j = 0; j < 4; j++) {
                float x = v[2 * j], y = v[2 * j + 1];
                __nv_bfloat16 hx = __float2bfloat16(x), hy = __float2bfloat16(y);
                float lx = x - __bfloat162float(hx), ly = y - __bfloat162float(hy);
                hi[j] = bfpack(hx, hy);
                lo[j] = bfpack(__float2bfloat16(lx), __float2bfloat16(ly));
            }
            uint32_t rb = (uint32_t)r * 128;
            *(uint4*)(dA + rb + ((uint32_t)((c    ) ^ (r & 7)) << 4)) = make_uint4(hi[0], hi[1], hi[2], hi[3]);
            *(uint4*)(dA + rb + ((uint32_t)((c + 4) ^ (r & 7)) << 4)) = make_uint4(lo[0], lo[1], lo[2], lo[3]);
        }
    };

    stage(0, 0);
    CPA_WAIT0();
    __syncthreads();

    for (int st = 0; st < nst; st++) {
        const int buf = st & 1;
        if (st + 1 < nst) stage(st + 1, buf ^ 1);   // LDG/cp.async overlap MMAs below

        const uint32_t aBase = sAu + (uint32_t)buf * 16384u;
        const uint32_t bBase = sBu + (uint32_t)buf * 16384u;
#pragma unroll
        for (int kc = 0; kc < 2; kc++) {
            uint32_t ah[2][4], al[2][4];
#pragma unroll
            for (int t = 0; t < 2; t++) {
                int rowm = wm * 32 + t * 16 + (g & 1) * 8 + i2;
                uint32_t rb = (uint32_t)rowm * 128;
                LDMX4(ah[t], aBase + rb + ((uint32_t)((2 * kc + (g >> 1)    ) ^ (rowm & 7)) << 4));
                LDMX4(al[t], aBase + rb + ((uint32_t)((2 * kc + (g >> 1) + 4) ^ (rowm & 7)) << 4));
            }
#pragma unroll
            for (int p = 0; p < 4; p++) {
                int rn = wn * 64 + p * 16 + (g >> 1) * 8 + i2;
                uint32_t rb = (uint32_t)rn * 128;
                uint32_t bh[4], bl[4];
                LDMX4(bh, bBase + rb + ((uint32_t)((2 * kc + (g & 1)    ) ^ (rn & 7)) << 4));
                LDMX4(bl, bBase + rb + ((uint32_t)((2 * kc + (g & 1) + 4) ^ (rn & 7)) << 4));
#pragma unroll
                for (int t = 0; t < 2; t++) {
                    MMA(acc[t][2 * p],     ah[t], bh[0], bh[1]);
                    MMA(acc[t][2 * p + 1], ah[t], bh[2], bh[3]);
                    MMA(acc[t][2 * p],     ah[t], bl[0], bl[1]);
                    MMA(acc[t][2 * p + 1], ah[t], bl[2], bl[3]);
                    MMA(acc[t][2 * p],     al[t], bh[0], bh[1]);
                    MMA(acc[t][2 * p + 1], al[t], bh[2], bh[3]);
                }
            }
        }
        CPA_WAIT0();
        __syncthreads();
    }

    // ---- epilogue: write C and/or scatter-RED into R[ridx[row]] ----
    const int coln0 = nb + wn * 64;
#pragma unroll
    for (int t = 0; t < 2; t++) {
#pragma unroll
        for (int s = 0; s < 2; s++) {
            int row = row0 + wm * 32 + t * 16 + (lane >> 2) + s * 8;
            if (row >= M) continue;
            int drow = 0;
            if (RED_) drow = __ldg(&ridx[row]);
#pragma unroll
            for (int n8 = 0; n8 < 8; n8++) {
                int col = coln0 + n8 * 8 + 2 * (lane & 3);
                float ox = acc[t][n8][2 * s], oy = acc[t][n8][2 * s + 1];
                if (MODE == MODE_MSG) {
                    float2 h = *(const float2*)(P3 + (size_t)row * HID + col);
                    ox += h.x; oy += h.y;
                }
                if (MODE == MODE_OUT) {
                    float2 b = *(const float2*)(bias + col);
                    ox += b.x; oy += b.y;
                }
                if (MODE != MODE_CAT3) { ox = fmaxf(ox, 0.f); oy = fmaxf(oy, 0.f); }
                if (WRITE_) {
                    float2 o = make_float2(ox, oy);
                    *(float2*)(C + (size_t)row * HID + col) = o;
                    if (MODE == MODE_IN2 && C2 != nullptr)
                        *(float2*)(C2 + (size_t)row * HID + col) = o;
                }
                if (RED_) {
                    float* p = R + (size_t)drow * HID + col;
                    asm volatile("red.global.add.v2.f32 [%0], {%1,%2};"
                                 :: "l"(p), "f"(ox), "f"(oy) : "memory");
                }
            }
        }
    }
}

// ------- ALL weight transposes + bf16 splits in ONE launch -------
// segments (elems = HID*Kpad): A 40960 | B 40960 | H 3*65536 | LR 196608 | O 131072
__global__ void wsplit_all_k(
    const float* __restrict__ Wa, const float* __restrict__ Wb, const float* __restrict__ Wh,
    const float* __restrict__ Wlr, const float* __restrict__ Wo,
    __nv_bfloat16* __restrict__ ahi, __nv_bfloat16* __restrict__ alo,
    __nv_bfloat16* __restrict__ bhi, __nv_bfloat16* __restrict__ blo,
    __nv_bfloat16* __restrict__ hhi, __nv_bfloat16* __restrict__ hlo,
    __nv_bfloat16* __restrict__ lrhi, __nv_bfloat16* __restrict__ lrlo,
    __nv_bfloat16* __restrict__ ohi, __nv_bfloat16* __restrict__ olo)
{
    int idx = blockIdx.x * blockDim.x + threadIdx.x;
    if (idx >= 606208) return;
    const float* W; __nv_bfloat16 *hi, *lo; int K, Kpad, local;
    if (idx < 40960)       { local = idx;          W = Wa;  hi = ahi;  lo = alo;  K = 133; Kpad = 160; }
    else if (idx < 81920)  { local = idx - 40960;  W = Wb;  hi = bhi;  lo = blo;  K = 147; Kpad = 160; }
    else if (idx < 278528) { int l = idx - 81920; int d = l >> 16; local = l & 65535;
                             W = Wh + (size_t)d * 65536; hi = hhi + (size_t)d * 65536;
                             lo = hlo + (size_t)d * 65536; K = 256; Kpad = 256; }
    else if (idx < 475136) { local = idx - 278528; W = Wlr; hi = lrhi; lo = lrlo; K = 768; Kpad = 768; }
    else                   { local = idx - 475136; W = Wo;  hi = ohi;  lo = olo;  K = 512; Kpad = 512; }
    int n = local / Kpad, k = local - n * Kpad;
    float v = (k < K) ? W[(size_t)k * HID + n] : 0.f;
    __nv_bfloat16 h = __float2bfloat16(v);
    hi[local] = h;
    lo[local] = __float2bfloat16(v - __bfloat162float(h));
}

__global__ void zero_k(float4* __restrict__ dst, int n4)
{
    int i = blockIdx.x * blockDim.x + threadIdx.x;
    if (i < n4) dst[i] = make_float4(0.f, 0.f, 0.f, 0.f);
}

__global__ void copy_k(const float4* __restrict__ src, float4* __restrict__ dst, int n4)
{
    int i = blockIdx.x * blockDim.x + threadIdx.x;
    if (i < n4) dst[i] = src[i];
}

extern "C" void kernel_launch(void* const* d_in, const int* in_sizes, int n_in,
                              void* d_out, int out_size)
{
    const float* node_attr = (const float*)d_in[0];
    const float* edge_attr = (const float*)d_in[1];
    const int*   src       = (const int*)d_in[2];
    const int*   dst       = (const int*)d_in[3];
    const float* W_i_atom  = (const float*)d_in[4];
    const float* W_i_bond  = (const float*)d_in[5];
    const float* W_h       = (const float*)d_in[6];
    const float* W_o       = (const float*)d_in[7];
    const float* W_o_b     = (const float*)d_in[8];
    const float* W_lr      = (const float*)d_in[9];
    float* out = (float*)d_out;

    const int KA = 133, KB = 147;
    const int n_nodes = in_sizes[0] / KA;
    const int n_edges = in_sizes[2];

    float *h0n, *hnA, *hnB, *h0e, *ea, *eb, *agf, *h2;
    __nv_bfloat16 *wahi, *walo, *wbhi, *wblo, *whhi, *whlo, *wlrhi, *wlrlo, *wohi, *wolo;
    cudaGetSymbolAddress((void**)&h0n, g_h0_node);
    cudaGetSymbolAddress((void**)&hnA, g_hnA);
    cudaGetSymbolAddress((void**)&hnB, g_hnB);
    cudaGetSymbolAddress((void**)&h0e, g_h0_edge);
    cudaGetSymbolAddress((void**)&ea,  g_edge_a);
    cudaGetSymbolAddress((void**)&eb,  g_edge_b);
    cudaGetSymbolAddress((void**)&agf, g_aggF);
    cudaGetSymbolAddress((void**)&h2,  g_h2);
    cudaGetSymbolAddress((void**)&wahi, g_WtA_hi);   cudaGetSymbolAddress((void**)&walo, g_WtA_lo);
    cudaGetSymbolAddress((void**)&wbhi, g_WtB_hi);   cudaGetSymbolAddress((void**)&wblo, g_WtB_lo);
    cudaGetSymbolAddress((void**)&whhi, g_WtH_hi);   cudaGetSymbolAddress((void**)&whlo, g_WtH_lo);
    cudaGetSymbolAddress((void**)&wlrhi, g_WtLR_hi); cudaGetSymbolAddress((void**)&wlrlo, g_WtLR_lo);
    cudaGetSymbolAddress((void**)&wohi, g_WtO_hi);   cudaGetSymbolAddress((void**)&wolo, g_WtO_lo);

    cudaFuncSetAttribute((const void*)tgemm_k<MODE_IN2,  false, true >, cudaFuncAttributeMaxDynamicSharedMemorySize, SMEM_BYTES);
    cudaFuncSetAttribute((const void*)tgemm_k<MODE_IN2,  true,  true >, cudaFuncAttributeMaxDynamicSharedMemorySize, SMEM_BYTES);
    cudaFuncSetAttribute((const void*)tgemm_k<MODE_MSG,  true,  true >, cudaFuncAttributeMaxDynamicSharedMemorySize, SMEM_BYTES);
    cudaFuncSetAttribute((const void*)tgemm_k<MODE_MSG,  true,  false>, cudaFuncAttributeMaxDynamicSharedMemorySize, SMEM_BYTES);
    cudaFuncSetAttribute((const void*)tgemm_k<MODE_CAT3, false, true >, cudaFuncAttributeMaxDynamicSharedMemorySize, SMEM_BYTES);
    cudaFuncSetAttribute((const void*)tgemm_k<MODE_OUT,  false, true >, cudaFuncAttributeMaxDynamicSharedMemorySize, SMEM_BYTES);

    dim3 blk(256);
    dim3 gn((n_nodes + 127) / 128, 2);
    dim3 ge((n_edges + 127) / 128, 2);
    const int n4n = n_nodes * HID / 4;
    const int cpg = (n4n + 255) / 256;

    // [1] zero final-agg buffer (explicit kernel so the launch count is deterministic for ncu)
    zero_k<<<cpg, 256>>>((float4*)agf, n4n);
    // [2] all weight transposes + bf16 splits
    wsplit_all_k<<<(606208 + 255) / 256, 256>>>(W_i_atom, W_i_bond, W_h, W_lr, W_o,
        wahi, walo, wbhi, wblo, whhi, whlo, wlrhi, wlrlo, wohi, wolo);

    // [3] node proj: h0n = relu(x@Wa); C2 seeds hnA = h0n
    tgemm_k<MODE_IN2, false, true><<<gn, blk, SMEM_BYTES>>>(node_attr, wahi, walo,
        h0n, hnA, nullptr, nullptr, nullptr, nullptr, nullptr, nullptr, nullptr, n_nodes, KA, 160);
    // [4] edge proj: h0e = relu(x@Wb); RED rows into hnA[dst] -> hnA = hn after agg0
    tgemm_k<MODE_IN2, true, true><<<ge, blk, SMEM_BYTES>>>(edge_attr, wbhi, wblo,
        h0e, nullptr, hnA, dst, nullptr, nullptr, nullptr, nullptr, nullptr, n_edges, KB, 160);

    // [5] copy hnA -> hnB; [6] MSG0 (this is the launch ncu -s 5 captures)
    copy_k<<<cpg, 256>>>((const float4*)hnA, (float4*)hnB, n4n);
    tgemm_k<MODE_MSG, true, true><<<ge, blk, SMEM_BYTES>>>(nullptr,
        whhi + 0 * (size_t)HID * HID, whlo + 0 * (size_t)HID * HID,
        ea, nullptr, hnB, dst, hnA, h0e, h0e, src, nullptr, n_edges, HID, HID);
    // depth 1
    copy_k<<<cpg, 256>>>((const float4*)hnB, (float4*)hnA, n4n);
    tgemm_k<MODE_MSG, true, true><<<ge, blk, SMEM_BYTES>>>(nullptr,
        whhi + 1 * (size_t)HID * HID, whlo + 1 * (size_t)HID * HID,
        eb, nullptr, hnA, dst, hnB, ea, h0e, src, nullptr, n_edges, HID, HID);
    // depth 2: no C write; RED into agf (pre-zeroed)
    tgemm_k<MODE_MSG, true, false><<<ge, blk, SMEM_BYTES>>>(nullptr,
        whhi + 2 * (size_t)HID * HID, whlo + 2 * (size_t)HID * HID,
        nullptr, nullptr, agf, dst, hnA, eb, h0e, src, nullptr, n_edges, HID, HID);

    // readout: h2 = [agf, hnA, h0n] @ W_lr ; out = relu([h2, h0n] @ W_o + b)
    tgemm_k<MODE_CAT3, false, true><<<gn, blk, SMEM_BYTES>>>(nullptr, wlrhi, wlrlo,
        h2, nullptr, nullptr, nullptr, agf, hnA, h0n, nullptr, nullptr, n_nodes, 768, 768);
    tgemm_k<MODE_OUT, false, true><<<gn, blk, SMEM_BYTES>>>(nullptr, wohi, wolo,
        out, nullptr, nullptr, nullptr, h2, h0n, nullptr, nullptr, W_o_b, n_nodes, 512, 512);
}

// round 6
// speedup vs baseline: 2.2612x; 1.0616x over previous
#include <cuda_runtime.h>
#include <cuda_bf16.h>
#include <cstdint>

#define HID 256
#define MAXN 100000
#define MAXE 400000
#define MAXN_PAD 100096   // MAXN rounded to 128

// ---------------- scratch (device globals; no allocation allowed) ----------------
__device__ float g_h0_node[(size_t)MAXN * HID];
__device__ float g_hnA    [(size_t)MAXN * HID];
__device__ float g_hnB    [(size_t)MAXN * HID];
__device__ float g_h0_edge[(size_t)MAXE * HID];
__device__ float g_edge_a [(size_t)MAXE * HID];
__device__ float g_edge_b [(size_t)MAXE * HID];
__device__ float g_aggF   [(size_t)MAXN * HID];
__device__ float g_h2     [(size_t)MAXN * HID];
// padded fp32 inputs (stride 160, zero-padded; tails never written -> stay zero)
__device__ __align__(16) float g_padN[(size_t)MAXN_PAD * 160];
__device__ __align__(16) float g_padE[(size_t)MAXE * 160];

// transposed + bf16-split weights: Wt[n][k], K-major, zero-padded to Kpad
__device__ __align__(16) __nv_bfloat16 g_WtA_hi[(size_t)HID * 160];
__device__ __align__(16) __nv_bfloat16 g_WtA_lo[(size_t)HID * 160];
__device__ __align__(16) __nv_bfloat16 g_WtB_hi[(size_t)HID * 160];
__device__ __align__(16) __nv_bfloat16 g_WtB_lo[(size_t)HID * 160];
__device__ __align__(16) __nv_bfloat16 g_WtH_hi[(size_t)3 * HID * HID];
__device__ __align__(16) __nv_bfloat16 g_WtH_lo[(size_t)3 * HID * HID];
__device__ __align__(16) __nv_bfloat16 g_WtLR_hi[(size_t)HID * 768];
__device__ __align__(16) __nv_bfloat16 g_WtLR_lo[(size_t)HID * 768];
__device__ __align__(16) __nv_bfloat16 g_WtO_hi [(size_t)HID * 512];
__device__ __align__(16) __nv_bfloat16 g_WtO_lo [(size_t)HID * 512];

__device__ __forceinline__ uint32_t smem_u32(const void* p) {
    uint32_t a;
    asm("{ .reg .u64 t; cvta.to.shared.u64 t, %1; cvt.u32.u64 %0, t; }" : "=r"(a) : "l"(p));
    return a;
}

#define LDMX4(r, addr) \
    asm volatile("ldmatrix.sync.aligned.m8n8.x4.shared.b16 {%0,%1,%2,%3}, [%4];" \
        : "=r"((r)[0]), "=r"((r)[1]), "=r"((r)[2]), "=r"((r)[3]) : "r"(addr))

#define LDS64(v, addr) \
    asm volatile("ld.shared.v2.f32 {%0,%1}, [%2];" : "=f"((v).x), "=f"((v).y) : "r"(addr))

#define MMA(d, a, b0_, b1_) \
    asm volatile("mma.sync.aligned.m16n8k16.row.col.f32.bf16.bf16.f32 " \
        "{%0,%1,%2,%3}, {%4,%5,%6,%7}, {%8,%9}, {%0,%1,%2,%3};" \
        : "+f"((d)[0]), "+f"((d)[1]), "+f"((d)[2]), "+f"((d)[3]) \
        : "r"((a)[0]), "r"((a)[1]), "r"((a)[2]), "r"((a)[3]), "r"(b0_), "r"(b1_))

#define CPA16(dst_u32, src_ptr) \
    asm volatile("cp.async.cg.shared.global [%0], [%1], 16;" \
        :: "r"(dst_u32), "l"(src_ptr) : "memory")
#define CPA_COMMIT() asm volatile("cp.async.commit_group;" ::: "memory")
#define CPA_WAIT0()  asm volatile("cp.async.wait_group 0;" ::: "memory")

// split fp32 pair -> bf16x2 hi + bf16x2 lo (RN, exact residual)
__device__ __forceinline__ void split2(float x, float y, uint32_t& hi, uint32_t& lo) {
    asm("cvt.rn.bf16x2.f32 %0, %1, %2;" : "=r"(hi) : "f"(y), "f"(x));
    float fx = __uint_as_float(hi << 16);
    float fy = __uint_as_float(hi & 0xffff0000u);
    float lx = x - fx, ly = y - fy;
    asm("cvt.rn.bf16x2.f32 %0, %1, %2;" : "=r"(lo) : "f"(ly), "f"(lx));
}

enum { MODE_IN2 = 0, MODE_MSG = 1, MODE_CAT3 = 2, MODE_OUT = 3 };

// --------- bf16x3 tensor-core GEMM, fully-async double-buffered pipeline ---------
// Block tile 128(M) x 128(N), grid.y covers N=256. 8 warps: 4(M) x 2(N).
// smem per buffer: rawA fp32 [1 or 2 streams, 16KB each] + B bf16 hi|lo 16KB.
template<int MODE, bool RED_, bool WRITE_>
__global__ __launch_bounds__(256, 2)
void tgemm_k(const float* __restrict__ A,
             const __nv_bfloat16* __restrict__ Whi, const __nv_bfloat16* __restrict__ Wlo,
             float* __restrict__ C, float* __restrict__ C2, float* __restrict__ R,
             const int* __restrict__ ridx,
             const float* __restrict__ P1, const float* __restrict__ P2,
             const float* __restrict__ P3, const int* __restrict__ sidx,
             const float* __restrict__ bias, int M, int Kpad)
{
    constexpr int STREAMS = (MODE == MODE_MSG) ? 2 : 1;
    constexpr uint32_t BSZ = 16384u * (STREAMS + 1);

    extern __shared__ __align__(16) uint8_t smem[];
    const uint32_t sAu = smem_u32(smem);

    const int tid  = threadIdx.x;
    const int lane = tid & 31;
    const int wid  = tid >> 5;
    const int wm   = wid & 3;
    const int wn   = wid >> 2;
    const int row0 = blockIdx.x * 128;
    const int nb   = blockIdx.y * 128;

    float acc[2][8][4];
#pragma unroll
    for (int t = 0; t < 2; t++)
#pragma unroll
        for (int n = 0; n < 8; n++)
#pragma unroll
            for (int q = 0; q < 4; q++) acc[t][n][q] = 0.f;

    const int g   = lane >> 3;
    const int i2  = lane & 7;
    const int gid = lane >> 2;
    const int tig = lane & 3;
    const int nst = Kpad >> 5;

    // pure cp.async staging: raw fp32 A stream(s) + pre-split bf16 B
    auto stage = [&](int st, int buf) {
        const int k0 = st << 5;
        const uint32_t aB = sAu + (uint32_t)buf * BSZ;
        const uint32_t bB = aB + 16384u * STREAMS;
        // B tile: 128 n-rows x 32 k, hi|lo in 128B rows
#pragma unroll
        for (int it = 0; it < 4; it++) {
            int idx = it * 256 + tid;
            int var = idx >> 9, rem = idx & 511;
            int r = rem >> 2, c = rem & 3;
            const __nv_bfloat16* W = var ? Wlo : Whi;
            const __nv_bfloat16* srcp = W + (size_t)(nb + r) * Kpad + k0 + c * 8;
            uint32_t dst = bB + (uint32_t)r * 128 + ((uint32_t)((var * 4 + c) ^ (r & 7)) << 4);
            CPA16(dst, srcp);
        }
        // A tile(s): 128 rows x 32 k fp32, 16B chunks, xor-swizzled
#pragma unroll
        for (int it = 0; it < 4; it++) {
            int idx = it * 256 + tid;
            int r = idx >> 3, c = idx & 7;
            int grow = row0 + r;
            int gk = k0 + c * 4;
            uint32_t dst = aB + (uint32_t)r * 128 + ((uint32_t)(c ^ (r & 7)) << 4);
            const float* s0;
            if (MODE == MODE_IN2) {
                s0 = A + (size_t)grow * Kpad + gk;                  // padded input
            } else if (MODE == MODE_MSG) {
                int s = __ldg(&sidx[grow]);
                s0 = P1 + (size_t)s * HID + gk;
            } else if (MODE == MODE_CAT3) {
                const float* p = (gk < 256) ? P1 : (gk < 512) ? P2 : P3;
                s0 = p + (size_t)grow * HID + (gk & 255);
            } else {
                const float* p = (gk < 256) ? P1 : P2;
                s0 = p + (size_t)grow * HID + (gk & 255);
            }
            CPA16(dst, s0);
            if (MODE == MODE_MSG) {
                const float* s1 = P2 + (size_t)(grow ^ 1) * HID + gk;
                CPA16(dst + 16384u, s1);
            }
        }
        CPA_COMMIT();
    };

    stage(0, 0);
    CPA_WAIT0();
    __syncthreads();

    for (int st = 0; st < nst; st++) {
        const int buf = st & 1;
        if (st + 1 < nst) stage(st + 1, buf ^ 1);   // fully async; overlaps MMAs

        const uint32_t aBase = sAu + (uint32_t)buf * BSZ;
        const uint32_t bBase = aBase + 16384u * STREAMS;
#pragma unroll
        for (int kc = 0; kc < 2; kc++) {
            // build A fragments from raw fp32 smem (m16n8k16 standard mapping)
            uint32_t ah[2][4], al[2][4];
#pragma unroll
            for (int t = 0; t < 2; t++) {
                int rl = wm * 32 + t * 16 + gid;
                int k0 = kc * 16 + tig * 2;
#pragma unroll
                for (int q = 0; q < 4; q++) {
                    int rr = rl + ((q & 1) << 3);
                    int kk = k0 + ((q >> 1) << 3);
                    uint32_t off = aBase + (uint32_t)rr * 128
                                 + ((uint32_t)(((uint32_t)kk >> 2) ^ (rr & 7)) << 4)
                                 + ((uint32_t)(kk & 3) << 2);
                    float2 v; LDS64(v, off);
                    if (MODE == MODE_MSG) {
                        float2 w; LDS64(w, off + 16384u);
                        v.x -= w.x; v.y -= w.y;
                    }
                    split2(v.x, v.y, ah[t][q], al[t][q]);
                }
            }
#pragma unroll
            for (int p = 0; p < 4; p++) {
                int rn = wn * 64 + p * 16 + (g >> 1) * 8 + i2;
                uint32_t rb = (uint32_t)rn * 128;
                uint32_t bh[4], bl[4];
                LDMX4(bh, bBase + rb + ((uint32_t)((2 * kc + (g & 1)    ) ^ (rn & 7)) << 4));
                LDMX4(bl, bBase + rb + ((uint32_t)((2 * kc + (g & 1) + 4) ^ (rn & 7)) << 4));
#pragma unroll
                for (int t = 0; t < 2; t++) {
                    MMA(acc[t][2 * p],     ah[t], bh[0], bh[1]);
                    MMA(acc[t][2 * p + 1], ah[t], bh[2], bh[3]);
                    MMA(acc[t][2 * p],     ah[t], bl[0], bl[1]);
                    MMA(acc[t][2 * p + 1], ah[t], bl[2], bl[3]);
                    MMA(acc[t][2 * p],     al[t], bh[0], bh[1]);
                    MMA(acc[t][2 * p + 1], al[t], bh[2], bh[3]);
                }
            }
        }
        CPA_WAIT0();
        __syncthreads();
    }

    // ---- epilogue: write C and/or scatter-RED into R[ridx[row]] ----
    const int coln0 = nb + wn * 64;
#pragma unroll
    for (int t = 0; t < 2; t++) {
#pragma unroll
        for (int s = 0; s < 2; s++) {
            int row = row0 + wm * 32 + t * 16 + (lane >> 2) + s * 8;
            if (row >= M) continue;
            int drow = 0;
            if (RED_) drow = __ldg(&ridx[row]);
#pragma unroll
            for (int n8 = 0; n8 < 8; n8++) {
                int col = coln0 + n8 * 8 + 2 * (lane & 3);
                float ox = acc[t][n8][2 * s], oy = acc[t][n8][2 * s + 1];
                if (MODE == MODE_MSG) {
                    float2 h = *(const float2*)(P3 + (size_t)row * HID + col);
                    ox += h.x; oy += h.y;
                }
                if (MODE == MODE_OUT) {
                    float2 b = *(const float2*)(bias + col);
                    ox += b.x; oy += b.y;
                }
                if (MODE != MODE_CAT3) { ox = fmaxf(ox, 0.f); oy = fmaxf(oy, 0.f); }
                if (WRITE_) {
                    float2 o = make_float2(ox, oy);
                    *(float2*)(C + (size_t)row * HID + col) = o;
                    if (MODE == MODE_IN2 && C2 != nullptr)
                        *(float2*)(C2 + (size_t)row * HID + col) = o;
                }
                if (RED_) {
                    float* p = R + (size_t)drow * HID + col;
                    asm volatile("red.global.add.v2.f32 [%0], {%1,%2};"
                                 :: "l"(p), "f"(ox), "f"(oy) : "memory");
                }
            }
        }
    }
}

// ------- ALL weight transposes + bf16 splits in ONE launch -------
__global__ void wsplit_all_k(
    const float* __restrict__ Wa, const float* __restrict__ Wb, const float* __restrict__ Wh,
    const float* __restrict__ Wlr, const float* __restrict__ Wo,
    __nv_bfloat16* __restrict__ ahi, __nv_bfloat16* __restrict__ alo,
    __nv_bfloat16* __restrict__ bhi, __nv_bfloat16* __restrict__ blo,
    __nv_bfloat16* __restrict__ hhi, __nv_bfloat16* __restrict__ hlo,
    __nv_bfloat16* __restrict__ lrhi, __nv_bfloat16* __restrict__ lrlo,
    __nv_bfloat16* __restrict__ ohi, __nv_bfloat16* __restrict__ olo)
{
    int idx = blockIdx.x * blockDim.x + threadIdx.x;
    if (idx >= 606208) return;
    const float* W; __nv_bfloat16 *hi, *lo; int K, Kpad, local;
    if (idx < 40960)       { local = idx;          W = Wa;  hi = ahi;  lo = alo;  K = 133; Kpad = 160; }
    else if (idx < 81920)  { local = idx - 40960;  W = Wb;  hi = bhi;  lo = blo;  K = 147; Kpad = 160; }
    else if (idx < 278528) { int l = idx - 81920; int d = l >> 16; local = l & 65535;
                             W = Wh + (size_t)d * 65536; hi = hhi + (size_t)d * 65536;
                             lo = hlo + (size_t)d * 65536; K = 256; Kpad = 256; }
    else if (idx < 475136) { local = idx - 278528; W = Wlr; hi = lrhi; lo = lrlo; K = 768; Kpad = 768; }
    else                   { local = idx - 475136; W = Wo;  hi = ohi;  lo = olo;  K = 512; Kpad = 512; }
    int n = local / Kpad, k = local - n * Kpad;
    float v = (k < K) ? W[(size_t)k * HID + n] : 0.f;
    __nv_bfloat16 h = __float2bfloat16(v);
    hi[local] = h;
    lo[local] = __float2bfloat16(v - __bfloat162float(h));
}

// ------- pad raw inputs to stride-160 fp32 (16B-aligned rows for cp.async) -------
__global__ void pad_k(const float* __restrict__ na, const float* __restrict__ ea,
                      float* __restrict__ pn, float* __restrict__ pe,
                      int n_nodes, int n_edges)
{
    long long i = (long long)blockIdx.x * 256 + threadIdx.x;
    long long tn = (long long)n_nodes * 160;
    if (i < tn) {
        int row = (int)(i / 160), k = (int)(i - (long long)row * 160);
        pn[i] = (k < 133) ? na[(size_t)row * 133 + k] : 0.f;
        return;
    }
    i -= tn;
    long long te = (long long)n_edges * 160;
    if (i < te) {
        int row = (int)(i / 160), k = (int)(i - (long long)row * 160);
        pe[i] = (k < 147) ? ea[(size_t)row * 147 + k] : 0.f;
    }
}

__global__ void zero_k(float4* __restrict__ dst, int n4)
{
    int i = blockIdx.x * blockDim.x + threadIdx.x;
    if (i < n4) dst[i] = make_float4(0.f, 0.f, 0.f, 0.f);
}

__global__ void copy_k(const float4* __restrict__ src, float4* __restrict__ dst, int n4)
{
    int i = blockIdx.x * blockDim.x + threadIdx.x;
    if (i < n4) dst[i] = src[i];
}

extern "C" void kernel_launch(void* const* d_in, const int* in_sizes, int n_in,
                              void* d_out, int out_size)
{
    const float* node_attr = (const float*)d_in[0];
    const float* edge_attr = (const float*)d_in[1];
    const int*   src       = (const int*)d_in[2];
    const int*   dst       = (const int*)d_in[3];
    const float* W_i_atom  = (const float*)d_in[4];
    const float* W_i_bond  = (const float*)d_in[5];
    const float* W_h       = (const float*)d_in[6];
    const float* W_o       = (const float*)d_in[7];
    const float* W_o_b     = (const float*)d_in[8];
    const float* W_lr      = (const float*)d_in[9];
    float* out = (float*)d_out;

    const int n_nodes = in_sizes[0] / 133;
    const int n_edges = in_sizes[2];

    float *h0n, *hnA, *hnB, *h0e, *ea, *eb, *agf, *h2, *pn, *pe;
    __nv_bfloat16 *wahi, *walo, *wbhi, *wblo, *whhi, *whlo, *wlrhi, *wlrlo, *wohi, *wolo;
    cudaGetSymbolAddress((void**)&h0n, g_h0_node);
    cudaGetSymbolAddress((void**)&hnA, g_hnA);
    cudaGetSymbolAddress((void**)&hnB, g_hnB);
    cudaGetSymbolAddress((void**)&h0e, g_h0_edge);
    cudaGetSymbolAddress((void**)&ea,  g_edge_a);
    cudaGetSymbolAddress((void**)&eb,  g_edge_b);
    cudaGetSymbolAddress((void**)&agf, g_aggF);
    cudaGetSymbolAddress((void**)&h2,  g_h2);
    cudaGetSymbolAddress((void**)&pn,  g_padN);
    cudaGetSymbolAddress((void**)&pe,  g_padE);
    cudaGetSymbolAddress((void**)&wahi, g_WtA_hi);   cudaGetSymbolAddress((void**)&walo, g_WtA_lo);
    cudaGetSymbolAddress((void**)&wbhi, g_WtB_hi);   cudaGetSymbolAddress((void**)&wblo, g_WtB_lo);
    cudaGetSymbolAddress((void**)&whhi, g_WtH_hi);   cudaGetSymbolAddress((void**)&whlo, g_WtH_lo);
    cudaGetSymbolAddress((void**)&wlrhi, g_WtLR_hi); cudaGetSymbolAddress((void**)&wlrlo, g_WtLR_lo);
    cudaGetSymbolAddress((void**)&wohi, g_WtO_hi);   cudaGetSymbolAddress((void**)&wolo, g_WtO_lo);

    // dynamic smem: MSG 96KB (2 A streams), others 64KB
    cudaFuncSetAttribute((const void*)tgemm_k<MODE_IN2,  false, true >, cudaFuncAttributeMaxDynamicSharedMemorySize, 65536);
    cudaFuncSetAttribute((const void*)tgemm_k<MODE_IN2,  true,  true >, cudaFuncAttributeMaxDynamicSharedMemorySize, 65536);
    cudaFuncSetAttribute((const void*)tgemm_k<MODE_MSG,  true,  true >, cudaFuncAttributeMaxDynamicSharedMemorySize, 98304);
    cudaFuncSetAttribute((const void*)tgemm_k<MODE_MSG,  true,  false>, cudaFuncAttributeMaxDynamicSharedMemorySize, 98304);
    cudaFuncSetAttribute((const void*)tgemm_k<MODE_CAT3, false, true >, cudaFuncAttributeMaxDynamicSharedMemorySize, 65536);
    cudaFuncSetAttribute((const void*)tgemm_k<MODE_OUT,  false, true >, cudaFuncAttributeMaxDynamicSharedMemorySize, 65536);

    dim3 blk(256);
    dim3 gn((n_nodes + 127) / 128, 2);
    dim3 ge((n_edges + 127) / 128, 2);
    const int n4n = n_nodes * HID / 4;
    const int cpg = (n4n + 255) / 256;
    const long long padtot = (long long)n_nodes * 160 + (long long)n_edges * 160;

    // [1] weights transpose+split  [2] pad inputs
    wsplit_all_k<<<(606208 + 255) / 256, 256>>>(W_i_atom, W_i_bond, W_h, W_lr, W_o,
        wahi, walo, wbhi, wblo, whhi, whlo, wlrhi, wlrlo, wohi, wolo);
    pad_k<<<(int)((padtot + 255) / 256), 256>>>(node_attr, edge_attr, pn, pe, n_nodes, n_edges);

    // [3] node proj: h0n = relu(Xn@Wa); C2 seeds hnA = h0n
    tgemm_k<MODE_IN2, false, true><<<gn, blk, 65536>>>(pn, wahi, walo,
        h0n, hnA, nullptr, nullptr, nullptr, nullptr, nullptr, nullptr, nullptr, n_nodes, 160);
    // [4] edge proj: h0e = relu(Xe@Wb); RED rows into hnA[dst]
    tgemm_k<MODE_IN2, true, true><<<ge, blk, 65536>>>(pe, wbhi, wblo,
        h0e, nullptr, hnA, dst, nullptr, nullptr, nullptr, nullptr, nullptr, n_edges, 160);

    // [5] copy hnA -> hnB ; [6] MSG0 (ncu -s 5 captures this)
    copy_k<<<cpg, 256>>>((const float4*)hnA, (float4*)hnB, n4n);
    tgemm_k<MODE_MSG, true, true><<<ge, blk, 98304>>>(nullptr,
        whhi + 0 * (size_t)HID * HID, whlo + 0 * (size_t)HID * HID,
        ea, nullptr, hnB, dst, hnA, h0e, h0e, src, nullptr, n_edges, HID);
    // zero agf (needed before MSG2)
    zero_k<<<cpg, 256>>>((float4*)agf, n4n);
    // depth 1
    copy_k<<<cpg, 256>>>((const float4*)hnB, (float4*)hnA, n4n);
    tgemm_k<MODE_MSG, true, true><<<ge, blk, 98304>>>(nullptr,
        whhi + 1 * (size_t)HID * HID, whlo + 1 * (size_t)HID * HID,
        eb, nullptr, hnA, dst, hnB, ea, h0e, src, nullptr, n_edges, HID);
    // depth 2: no C write; RED into agf
    tgemm_k<MODE_MSG, true, false><<<ge, blk, 98304>>>(nullptr,
        whhi + 2 * (size_t)HID * HID, whlo + 2 * (size_t)HID * HID,
        nullptr, nullptr, agf, dst, hnA, eb, h0e, src, nullptr, n_edges, HID);

    // readout
    tgemm_k<MODE_CAT3, false, true><<<gn, blk, 65536>>>(nullptr, wlrhi, wlrlo,
        h2, nullptr, nullptr, nullptr, agf, hnA, h0n, nullptr, nullptr, n_nodes, 768);
    tgemm_k<MODE_OUT, false, true><<<gn, blk, 65536>>>(nullptr, wohi, wolo,
        out, nullptr, nullptr, nullptr, h2, h0n, nullptr, nullptr, W_o_b, n_nodes, 512);
}

// round 7
// speedup vs baseline: 2.3509x; 1.0397x over previous
#include <cuda_runtime.h>
#include <cuda_bf16.h>
#include <cstdint>

#define HID 256
#define MAXN 100000
#define MAXE 400000
#define MAXN_PAD 100096

// ---------------- scratch (device globals; no allocation allowed) ----------------
__device__ float g_h0_node[(size_t)MAXN * HID];
__device__ float g_hnA    [(size_t)MAXN * HID];
__device__ float g_hnB    [(size_t)MAXN * HID];
__device__ float g_h0_edge[(size_t)MAXE * HID];
__device__ float g_edge_a [(size_t)MAXE * HID];
__device__ float g_edge_b [(size_t)MAXE * HID];
__device__ float g_aggF   [(size_t)MAXN * HID];
__device__ float g_h2     [(size_t)MAXN * HID];
__device__ __align__(16) float g_padN[(size_t)MAXN_PAD * 160];
__device__ __align__(16) float g_padE[(size_t)MAXE * 160];

// transposed + bf16-split weights: Wt[n][k], K-major, zero-padded to Kpad
__device__ __align__(16) __nv_bfloat16 g_WtA_hi[(size_t)HID * 160];
__device__ __align__(16) __nv_bfloat16 g_WtA_lo[(size_t)HID * 160];
__device__ __align__(16) __nv_bfloat16 g_WtB_hi[(size_t)HID * 160];
__device__ __align__(16) __nv_bfloat16 g_WtB_lo[(size_t)HID * 160];
__device__ __align__(16) __nv_bfloat16 g_WtH_hi[(size_t)3 * HID * HID];
__device__ __align__(16) __nv_bfloat16 g_WtH_lo[(size_t)3 * HID * HID];
__device__ __align__(16) __nv_bfloat16 g_WtLR_hi[(size_t)HID * 768];
__device__ __align__(16) __nv_bfloat16 g_WtLR_lo[(size_t)HID * 768];
__device__ __align__(16) __nv_bfloat16 g_WtO_hi [(size_t)HID * 512];
__device__ __align__(16) __nv_bfloat16 g_WtO_lo [(size_t)HID * 512];

__device__ __forceinline__ uint32_t smem_u32(const void* p) {
    uint32_t a;
    asm("{ .reg .u64 t; cvta.to.shared.u64 t, %1; cvt.u32.u64 %0, t; }" : "=r"(a) : "l"(p));
    return a;
}

#define LDMX4(r, addr) \
    asm volatile("ldmatrix.sync.aligned.m8n8.x4.shared.b16 {%0,%1,%2,%3}, [%4];" \
        : "=r"((r)[0]), "=r"((r)[1]), "=r"((r)[2]), "=r"((r)[3]) : "r"(addr))

#define LDS64(v, addr) \
    asm volatile("ld.shared.v2.f32 {%0,%1}, [%2];" : "=f"((v).x), "=f"((v).y) : "r"(addr))

#define MMA(d, a, b0_, b1_) \
    asm volatile("mma.sync.aligned.m16n8k16.row.col.f32.bf16.bf16.f32 " \
        "{%0,%1,%2,%3}, {%4,%5,%6,%7}, {%8,%9}, {%0,%1,%2,%3};" \
        : "+f"((d)[0]), "+f"((d)[1]), "+f"((d)[2]), "+f"((d)[3]) \
        : "r"((a)[0]), "r"((a)[1]), "r"((a)[2]), "r"((a)[3]), "r"(b0_), "r"(b1_))

#define CPA16(dst_u32, src_ptr) \
    asm volatile("cp.async.cg.shared.global [%0], [%1], 16;" \
        :: "r"(dst_u32), "l"(src_ptr) : "memory")
#define CPA_COMMIT() asm volatile("cp.async.commit_group;" ::: "memory")
#define CPA_WAIT0()  asm volatile("cp.async.wait_group 0;" ::: "memory")

// split fp32 pair -> bf16x2 hi + bf16x2 lo (RN, exact residual)
__device__ __forceinline__ void split2(float x, float y, uint32_t& hi, uint32_t& lo) {
    asm("cvt.rn.bf16x2.f32 %0, %1, %2;" : "=r"(hi) : "f"(y), "f"(x));
    float fx = __uint_as_float(hi << 16);
    float fy = __uint_as_float(hi & 0xffff0000u);
    float lx = x - fx, ly = y - fy;
    asm("cvt.rn.bf16x2.f32 %0, %1, %2;" : "=r"(lo) : "f"(ly), "f"(lx));
}

enum { MODE_IN2 = 0, MODE_MSG = 1, MODE_CAT3 = 2, MODE_OUT = 3 };

// --------- bf16x3 tensor-core GEMM, async pipeline, dependency-spaced MMA passes ---------
// Block tile 128(M) x 128(N), grid.y covers N=256. 8 warps: 4(M) x 2(N).
template<int MODE, bool RED_, bool WRITE_>
__global__ __launch_bounds__(256, 2)
void tgemm_k(const float* __restrict__ A,
             const __nv_bfloat16* __restrict__ Whi, const __nv_bfloat16* __restrict__ Wlo,
             float* __restrict__ C, float* __restrict__ C2, float* __restrict__ R,
             const int* __restrict__ ridx,
             const float* __restrict__ P1, const float* __restrict__ P2,
             const float* __restrict__ P3, const int* __restrict__ sidx,
             const float* __restrict__ bias, int M, int Kpad)
{
    constexpr int STREAMS = (MODE == MODE_MSG) ? 2 : 1;
    constexpr uint32_t BSZ = 16384u * (STREAMS + 1);

    extern __shared__ __align__(16) uint8_t smem[];
    const uint32_t sAu = smem_u32(smem);

    const int tid  = threadIdx.x;
    const int lane = tid & 31;
    const int wid  = tid >> 5;
    const int wm   = wid & 3;
    const int wn   = wid >> 2;
    const int row0 = blockIdx.x * 128;
    const int nb   = blockIdx.y * 128;

    float acc[2][8][4];
#pragma unroll
    for (int t = 0; t < 2; t++)
#pragma unroll
        for (int n = 0; n < 8; n++)
#pragma unroll
            for (int q = 0; q < 4; q++) acc[t][n][q] = 0.f;

    const int g   = lane >> 3;
    const int i2  = lane & 7;
    const int gid = lane >> 2;
    const int tig = lane & 3;
    const int nst = Kpad >> 5;

    auto stage = [&](int st, int buf) {
        const int k0 = st << 5;
        const uint32_t aB = sAu + (uint32_t)buf * BSZ;
        const uint32_t bB = aB + 16384u * STREAMS;
#pragma unroll
        for (int it = 0; it < 4; it++) {
            int idx = it * 256 + tid;
            int var = idx >> 9, rem = idx & 511;
            int r = rem >> 2, c = rem & 3;
            const __nv_bfloat16* W = var ? Wlo : Whi;
            const __nv_bfloat16* srcp = W + (size_t)(nb + r) * Kpad + k0 + c * 8;
            uint32_t dst = bB + (uint32_t)r * 128 + ((uint32_t)((var * 4 + c) ^ (r & 7)) << 4);
            CPA16(dst, srcp);
        }
#pragma unroll
        for (int it = 0; it < 4; it++) {
            int idx = it * 256 + tid;
            int r = idx >> 3, c = idx & 7;
            int grow = row0 + r;
            int gk = k0 + c * 4;
            uint32_t dst = aB + (uint32_t)r * 128 + ((uint32_t)(c ^ (r & 7)) << 4);
            const float* s0;
            if (MODE == MODE_IN2) {
                s0 = A + (size_t)grow * Kpad + gk;
            } else if (MODE == MODE_MSG) {
                int s = __ldg(&sidx[grow]);
                s0 = P1 + (size_t)s * HID + gk;
            } else if (MODE == MODE_CAT3) {
                const float* p = (gk < 256) ? P1 : (gk < 512) ? P2 : P3;
                s0 = p + (size_t)grow * HID + (gk & 255);
            } else {
                const float* p = (gk < 256) ? P1 : P2;
                s0 = p + (size_t)grow * HID + (gk & 255);
            }
            CPA16(dst, s0);
            if (MODE == MODE_MSG) {
                const float* s1 = P2 + (size_t)(grow ^ 1) * HID + gk;
                CPA16(dst + 16384u, s1);
            }
        }
        CPA_COMMIT();
    };

    stage(0, 0);
    CPA_WAIT0();
    __syncthreads();

    for (int st = 0; st < nst; st++) {
        const int buf = st & 1;
        if (st + 1 < nst) stage(st + 1, buf ^ 1);

        const uint32_t aBase = sAu + (uint32_t)buf * BSZ;
        const uint32_t bBase = aBase + 16384u * STREAMS;

        // ---- build A fragments for BOTH kc chunks up-front (batch the LDS/cvt chains) ----
        uint32_t ah[2][2][4], al[2][2][4];   // [kc][t][q]
#pragma unroll
        for (int kc = 0; kc < 2; kc++) {
#pragma unroll
            for (int t = 0; t < 2; t++) {
                int rl = wm * 32 + t * 16 + gid;
                int kbase = kc * 16 + tig * 2;
#pragma unroll
                for (int q = 0; q < 4; q++) {
                    int rr = rl + ((q & 1) << 3);
                    int kk = kbase + ((q >> 1) << 3);
                    uint32_t off = aBase + (uint32_t)rr * 128
                                 + ((uint32_t)(((uint32_t)kk >> 2) ^ (rr & 7)) << 4)
                                 + ((uint32_t)(kk & 3) << 2);
                    float2 v; LDS64(v, off);
                    if (MODE == MODE_MSG) {
                        float2 w; LDS64(w, off + 16384u);
                        v.x -= w.x; v.y -= w.y;
                    }
                    split2(v.x, v.y, ah[kc][t][q], al[kc][t][q]);
                }
            }
        }

        // ---- MMA phase: 3 passes x 16 independent accumulators per kc ----
#pragma unroll
        for (int kc = 0; kc < 2; kc++) {
            uint32_t bfr[4][4];
            // B-hi fragments for all 4 column groups
#pragma unroll
            for (int p = 0; p < 4; p++) {
                int rn = wn * 64 + p * 16 + (g >> 1) * 8 + i2;
                LDMX4(bfr[p], bBase + (uint32_t)rn * 128
                              + ((uint32_t)((2 * kc + (g & 1)) ^ (rn & 7)) << 4));
            }
            // pass 1: ah x bh  (16 MMAs, all distinct accs)
#pragma unroll
            for (int p = 0; p < 4; p++)
#pragma unroll
                for (int t = 0; t < 2; t++) {
                    MMA(acc[t][2 * p],     ah[kc][t], bfr[p][0], bfr[p][1]);
                    MMA(acc[t][2 * p + 1], ah[kc][t], bfr[p][2], bfr[p][3]);
                }
            // pass 2: al x bh
#pragma unroll
            for (int p = 0; p < 4; p++)
#pragma unroll
                for (int t = 0; t < 2; t++) {
                    MMA(acc[t][2 * p],     al[kc][t], bfr[p][0], bfr[p][1]);
                    MMA(acc[t][2 * p + 1], al[kc][t], bfr[p][2], bfr[p][3]);
                }
            // reload fragment regs with B-lo
#pragma unroll
            for (int p = 0; p < 4; p++) {
                int rn = wn * 64 + p * 16 + (g >> 1) * 8 + i2;
                LDMX4(bfr[p], bBase + (uint32_t)rn * 128
                              + ((uint32_t)((2 * kc + (g & 1) + 4) ^ (rn & 7)) << 4));
            }
            // pass 3: ah x bl
#pragma unroll
            for (int p = 0; p < 4; p++)
#pragma unroll
                for (int t = 0; t < 2; t++) {
                    MMA(acc[t][2 * p],     ah[kc][t], bfr[p][0], bfr[p][1]);
                    MMA(acc[t][2 * p + 1], ah[kc][t], bfr[p][2], bfr[p][3]);
                }
        }
        CPA_WAIT0();
        __syncthreads();
    }

    // ---- epilogue: write C and/or scatter-RED into R[ridx[row]] ----
    const int coln0 = nb + wn * 64;
#pragma unroll
    for (int t = 0; t < 2; t++) {
#pragma unroll
        for (int s = 0; s < 2; s++) {
            int row = row0 + wm * 32 + t * 16 + (lane >> 2) + s * 8;
            if (row >= M) continue;
            int drow = 0;
            if (RED_) drow = __ldg(&ridx[row]);
#pragma unroll
            for (int n8 = 0; n8 < 8; n8++) {
                int col = coln0 + n8 * 8 + 2 * (lane & 3);
                float ox = acc[t][n8][2 * s], oy = acc[t][n8][2 * s + 1];
                if (MODE == MODE_MSG) {
                    float2 h = *(const float2*)(P3 + (size_t)row * HID + col);
                    ox += h.x; oy += h.y;
                }
                if (MODE == MODE_OUT) {
                    float2 b = *(const float2*)(bias + col);
                    ox += b.x; oy += b.y;
                }
                if (MODE != MODE_CAT3) { ox = fmaxf(ox, 0.f); oy = fmaxf(oy, 0.f); }
                if (WRITE_) {
                    float2 o = make_float2(ox, oy);
                    *(float2*)(C + (size_t)row * HID + col) = o;
                    if (MODE == MODE_IN2 && C2 != nullptr)
                        *(float2*)(C2 + (size_t)row * HID + col) = o;
                }
                if (RED_) {
                    float* p = R + (size_t)drow * HID + col;
                    asm volatile("red.global.add.v2.f32 [%0], {%1,%2};"
                                 :: "l"(p), "f"(ox), "f"(oy) : "memory");
                }
            }
        }
    }
}

// ------- ALL weight transposes + bf16 splits in ONE launch -------
__global__ void wsplit_all_k(
    const float* __restrict__ Wa, const float* __restrict__ Wb, const float* __restrict__ Wh,
    const float* __restrict__ Wlr, const float* __restrict__ Wo,
    __nv_bfloat16* __restrict__ ahi, __nv_bfloat16* __restrict__ alo,
    __nv_bfloat16* __restrict__ bhi, __nv_bfloat16* __restrict__ blo,
    __nv_bfloat16* __restrict__ hhi, __nv_bfloat16* __restrict__ hlo,
    __nv_bfloat16* __restrict__ lrhi, __nv_bfloat16* __restrict__ lrlo,
    __nv_bfloat16* __restrict__ ohi, __nv_bfloat16* __restrict__ olo)
{
    int idx = blockIdx.x * blockDim.x + threadIdx.x;
    if (idx >= 606208) return;
    const float* W; __nv_bfloat16 *hi, *lo; int K, Kpad, local;
    if (idx < 40960)       { local = idx;          W = Wa;  hi = ahi;  lo = alo;  K = 133; Kpad = 160; }
    else if (idx < 81920)  { local = idx - 40960;  W = Wb;  hi = bhi;  lo = blo;  K = 147; Kpad = 160; }
    else if (idx < 278528) { int l = idx - 81920; int d = l >> 16; local = l & 65535;
                             W = Wh + (size_t)d * 65536; hi = hhi + (size_t)d * 65536;
                             lo = hlo + (size_t)d * 65536; K = 256; Kpad = 256; }
    else if (idx < 475136) { local = idx - 278528; W = Wlr; hi = lrhi; lo = lrlo; K = 768; Kpad = 768; }
    else                   { local = idx - 475136; W = Wo;  hi = ohi;  lo = olo;  K = 512; Kpad = 512; }
    int n = local / Kpad, k = local - n * Kpad;
    float v = (k < K) ? W[(size_t)k * HID + n] : 0.f;
    __nv_bfloat16 h = __float2bfloat16(v);
    hi[local] = h;
    lo[local] = __float2bfloat16(v - __bfloat162float(h));
}

// ------- pad raw inputs to stride-160 fp32 -------
__global__ void pad_k(const float* __restrict__ na, const float* __restrict__ ea,
                      float* __restrict__ pn, float* __restrict__ pe,
                      int n_nodes, int n_edges)
{
    long long i = (long long)blockIdx.x * 256 + threadIdx.x;
    long long tn = (long long)n_nodes * 160;
    if (i < tn) {
        int row = (int)(i / 160), k = (int)(i - (long long)row * 160);
        pn[i] = (k < 133) ? na[(size_t)row * 133 + k] : 0.f;
        return;
    }
    i -= tn;
    long long te = (long long)n_edges * 160;
    if (i < te) {
        int row = (int)(i / 160), k = (int)(i - (long long)row * 160);
        pe[i] = (k < 147) ? ea[(size_t)row * 147 + k] : 0.f;
    }
}

__global__ void zero_k(float4* __restrict__ dst, int n4)
{
    int i = blockIdx.x * blockDim.x + threadIdx.x;
    if (i < n4) dst[i] = make_float4(0.f, 0.f, 0.f, 0.f);
}

__global__ void copy_k(const float4* __restrict__ src, float4* __restrict__ dst, int n4)
{
    int i = blockIdx.x * blockDim.x + threadIdx.x;
    if (i < n4) dst[i] = src[i];
}

extern "C" void kernel_launch(void* const* d_in, const int* in_sizes, int n_in,
                              void* d_out, int out_size)
{
    const float* node_attr = (const float*)d_in[0];
    const float* edge_attr = (const float*)d_in[1];
    const int*   src       = (const int*)d_in[2];
    const int*   dst       = (const int*)d_in[3];
    const float* W_i_atom  = (const float*)d_in[4];
    const float* W_i_bond  = (const float*)d_in[5];
    const float* W_h       = (const float*)d_in[6];
    const float* W_o       = (const float*)d_in[7];
    const float* W_o_b     = (const float*)d_in[8];
    const float* W_lr      = (const float*)d_in[9];
    float* out = (float*)d_out;

    const int n_nodes = in_sizes[0] / 133;
    const int n_edges = in_sizes[2];

    float *h0n, *hnA, *hnB, *h0e, *ea, *eb, *agf, *h2, *pn, *pe;
    __nv_bfloat16 *wahi, *walo, *wbhi, *wblo, *whhi, *whlo, *wlrhi, *wlrlo, *wohi, *wolo;
    cudaGetSymbolAddress((void**)&h0n, g_h0_node);
    cudaGetSymbolAddress((void**)&hnA, g_hnA);
    cudaGetSymbolAddress((void**)&hnB, g_hnB);
    cudaGetSymbolAddress((void**)&h0e, g_h0_edge);
    cudaGetSymbolAddress((void**)&ea,  g_edge_a);
    cudaGetSymbolAddress((void**)&eb,  g_edge_b);
    cudaGetSymbolAddress((void**)&agf, g_aggF);
    cudaGetSymbolAddress((void**)&h2,  g_h2);
    cudaGetSymbolAddress((void**)&pn,  g_padN);
    cudaGetSymbolAddress((void**)&pe,  g_padE);
    cudaGetSymbolAddress((void**)&wahi, g_WtA_hi);   cudaGetSymbolAddress((void**)&walo, g_WtA_lo);
    cudaGetSymbolAddress((void**)&wbhi, g_WtB_hi);   cudaGetSymbolAddress((void**)&wblo, g_WtB_lo);
    cudaGetSymbolAddress((void**)&whhi, g_WtH_hi);   cudaGetSymbolAddress((void**)&whlo, g_WtH_lo);
    cudaGetSymbolAddress((void**)&wlrhi, g_WtLR_hi); cudaGetSymbolAddress((void**)&wlrlo, g_WtLR_lo);
    cudaGetSymbolAddress((void**)&wohi, g_WtO_hi);   cudaGetSymbolAddress((void**)&wolo, g_WtO_lo);

    cudaFuncSetAttribute((const void*)tgemm_k<MODE_IN2,  false, true >, cudaFuncAttributeMaxDynamicSharedMemorySize, 65536);
    cudaFuncSetAttribute((const void*)tgemm_k<MODE_IN2,  true,  true >, cudaFuncAttributeMaxDynamicSharedMemorySize, 65536);
    cudaFuncSetAttribute((const void*)tgemm_k<MODE_MSG,  true,  true >, cudaFuncAttributeMaxDynamicSharedMemorySize, 98304);
    cudaFuncSetAttribute((const void*)tgemm_k<MODE_MSG,  true,  false>, cudaFuncAttributeMaxDynamicSharedMemorySize, 98304);
    cudaFuncSetAttribute((const void*)tgemm_k<MODE_CAT3, false, true >, cudaFuncAttributeMaxDynamicSharedMemorySize, 65536);
    cudaFuncSetAttribute((const void*)tgemm_k<MODE_OUT,  false, true >, cudaFuncAttributeMaxDynamicSharedMemorySize, 65536);

    dim3 blk(256);
    dim3 gn((n_nodes + 127) / 128, 2);
    dim3 ge((n_edges + 127) / 128, 2);
    const int n4n = n_nodes * HID / 4;
    const int cpg = (n4n + 255) / 256;
    const long long padtot = (long long)n_nodes * 160 + (long long)n_edges * 160;

    wsplit_all_k<<<(606208 + 255) / 256, 256>>>(W_i_atom, W_i_bond, W_h, W_lr, W_o,
        wahi, walo, wbhi, wblo, whhi, whlo, wlrhi, wlrlo, wohi, wolo);
    pad_k<<<(int)((padtot + 255) / 256), 256>>>(node_attr, edge_attr, pn, pe, n_nodes, n_edges);

    tgemm_k<MODE_IN2, false, true><<<gn, blk, 65536>>>(pn, wahi, walo,
        h0n, hnA, nullptr, nullptr, nullptr, nullptr, nullptr, nullptr, nullptr, n_nodes, 160);
    tgemm_k<MODE_IN2, true, true><<<ge, blk, 65536>>>(pe, wbhi, wblo,
        h0e, nullptr, hnA, dst, nullptr, nullptr, nullptr, nullptr, nullptr, n_edges, 160);

    copy_k<<<cpg, 256>>>((const float4*)hnA, (float4*)hnB, n4n);
    tgemm_k<MODE_MSG, true, true><<<ge, blk, 98304>>>(nullptr,
        whhi + 0 * (size_t)HID * HID, whlo + 0 * (size_t)HID * HID,
        ea, nullptr, hnB, dst, hnA, h0e, h0e, src, nullptr, n_edges, HID);
    zero_k<<<cpg, 256>>>((float4*)agf, n4n);
    copy_k<<<cpg, 256>>>((const float4*)hnB, (float4*)hnA, n4n);
    tgemm_k<MODE_MSG, true, true><<<ge, blk, 98304>>>(nullptr,
        whhi + 1 * (size_t)HID * HID, whlo + 1 * (size_t)HID * HID,
        eb, nullptr, hnA, dst, hnB, ea, h0e, src, nullptr, n_edges, HID);
    tgemm_k<MODE_MSG, true, false><<<ge, blk, 98304>>>(nullptr,
        whhi + 2 * (size_t)HID * HID, whlo + 2 * (size_t)HID * HID,
        nullptr, nullptr, agf, dst, hnA, eb, h0e, src, nullptr, n_edges, HID);

    tgemm_k<MODE_CAT3, false, true><<<gn, blk, 65536>>>(nullptr, wlrhi, wlrlo,
        h2, nullptr, nullptr, nullptr, agf, hnA, h0n, nullptr, nullptr, n_nodes, 768);
    tgemm_k<MODE_OUT, false, true><<<gn, blk, 65536>>>(nullptr, wohi, wolo,
        out, nullptr, nullptr, nullptr, h2, h0n, nullptr, nullptr, W_o_b, n_nodes, 512);
}